// round 11
// baseline (speedup 1.0000x reference)
#include <cuda_runtime.h>
#include <cuda_bf16.h>
#include <math.h>
#include <stdint.h>

// Problem dims
#define SQ   2048
#define DM   1024
#define NH   16
#define DK   64
#define BB   2
#define ROWS (BB*SQ)   // 4096
#define BHN  (BB*NH)   // 32

// ---------------- scratch (static device memory; no allocs allowed) ----------------
__device__ float g_Q  [ (size_t)ROWS*DM ];
__device__ float g_K  [ (size_t)ROWS*DM ];
__device__ float g_V  [ (size_t)ROWS*DM ];
__device__ float g_ctx[ (size_t)ROWS*DM ];
__device__ float g_fc [ (size_t)ROWS*DM ];
__device__ float g_attn[ (size_t)BHN*SQ*SQ ];            // attn dump when not in d_out
__device__ uint32_t g_maskbits[ (size_t)BB*SQ*SQ/32 ];   // 1 bit per (b,q,k)
__device__ int   g_maskmode;

// ---------------- mask dtype detection ----------------
__global__ void detect_mask_kernel(const void* __restrict__ mask)
{
    __shared__ int ok[3];
    int tid = threadIdx.x;
    if (tid < 3) ok[tid] = 1;
    __syncthreads();
    const unsigned int*   pi = (const unsigned int*)mask;
    const unsigned short* ps = (const unsigned short*)mask;
    bool i32ok = true, f32ok = true, bfok = true;
    for (int i = tid; i < 4096; i += 256) {
        unsigned int v = pi[i];
        if (v > 1u) i32ok = false;
        if (v != 0u && v != 0x3F800000u) f32ok = false;
    }
    for (int i = tid; i < 4096; i += 256) {
        unsigned short v = ps[i];
        if (v != 0 && v != 0x3F80) bfok = false;
    }
    if (!i32ok) atomicAnd(&ok[0], 0);
    if (!f32ok) atomicAnd(&ok[1], 0);
    if (!bfok)  atomicAnd(&ok[2], 0);
    __syncthreads();
    if (tid == 0)
        g_maskmode = ok[0] ? 0 : (ok[1] ? 1 : (ok[2] ? 3 : 2));
}

__device__ __forceinline__ bool mask_at(const void* __restrict__ mask, size_t idx, int mode)
{
    if (mode == 0) return ((const int*)mask)[idx] != 0;
    if (mode == 1) return ((const float*)mask)[idx] != 0.0f;
    if (mode == 2) return ((const unsigned char*)mask)[idx] != 0;
    return ((const unsigned short*)mask)[idx] != 0;
}

// mask -> bitmap: one warp per 32-bit word, ballot
__global__ void __launch_bounds__(256) mask_to_bits(const void* __restrict__ mask)
{
    const int w = blockIdx.x * 8 + (threadIdx.x >> 5);
    const int lane = threadIdx.x & 31;
    const int mode = g_maskmode;
    size_t idx = (size_t)w * 32 + lane;
    bool m = mask_at(mask, idx, mode);
    uint32_t bits = __ballot_sync(0xffffffffu, m);
    if (lane == 0) g_maskbits[w] = bits;
}

// ======================= helpers =======================
__device__ __forceinline__ uint32_t smem_u32(const void* p) {
    uint32_t a;
    asm("{ .reg .u64 t; cvta.to.shared.u64 t, %1; cvt.u32.u64 %0, t; }" : "=r"(a) : "l"(p));
    return a;
}
__device__ __forceinline__ uint32_t swz64(uint32_t b)  { return b ^ ((b >> 3) & 0x30); }
__device__ __forceinline__ uint32_t swz128(uint32_t b) { return b ^ ((b >> 3) & 0x70); }

// split f32 -> bf16 hi + bf16 lo
__device__ __forceinline__ void split4(float4 v, uint2& uh, uint2& ul)
{
    __nv_bfloat16 hx = __float2bfloat16(v.x), hy = __float2bfloat16(v.y);
    __nv_bfloat16 hz = __float2bfloat16(v.z), hw = __float2bfloat16(v.w);
    __nv_bfloat16 lx = __float2bfloat16(v.x - __bfloat162float(hx));
    __nv_bfloat16 ly = __float2bfloat16(v.y - __bfloat162float(hy));
    __nv_bfloat16 lz = __float2bfloat16(v.z - __bfloat162float(hz));
    __nv_bfloat16 lw = __float2bfloat16(v.w - __bfloat162float(hw));
    union { __nv_bfloat162 b2[2]; uint2 u; } th, tl;
    th.b2[0] = __halves2bfloat162(hx, hy); th.b2[1] = __halves2bfloat162(hz, hw);
    tl.b2[0] = __halves2bfloat162(lx, ly); tl.b2[1] = __halves2bfloat162(lz, lw);
    uh = th.u; ul = tl.u;
}

#define LDMX4(r, addr) \
    asm volatile("ldmatrix.sync.aligned.m8n8.x4.shared.b16 {%0,%1,%2,%3}, [%4];" \
        : "=r"((r)[0]), "=r"((r)[1]), "=r"((r)[2]), "=r"((r)[3]) : "r"(addr))

#define MMA_BF16(cc, a, b0_, b1_) \
    asm volatile("mma.sync.aligned.m16n8k16.row.col.f32.bf16.bf16.f32 " \
        "{%0,%1,%2,%3}, {%4,%5,%6,%7}, {%8,%9}, {%0,%1,%2,%3};" \
        : "+f"((cc)[0]), "+f"((cc)[1]), "+f"((cc)[2]), "+f"((cc)[3]) \
        : "r"((a)[0]), "r"((a)[1]), "r"((a)[2]), "r"((a)[3]), "r"(b0_), "r"(b1_))

// ======================= bf16x3 mma.sync GEMM, register-prefetch pipelined ==========
// MODE 0: dense  C[4096,1024] = A[4096,1024] * B[1024,1024]^T  (both K-major, ld=DM)
// MODE 2: pv     per bh: ctx = attn[2048,2048] @ V[2048,64]  (V transposed on load)
template<int MODE>
__global__ void __launch_bounds__(256, 2) mma_gemm(const float* __restrict__ Ap,
                                                   const float* __restrict__ Bp,
                                                   float* __restrict__ Cp)
{
    constexpr int BN    = (MODE == 2) ? 64 : 128;
    constexpr int NSTEP = (MODE == 0) ? 32 : 64;
    constexpr int BNW   = BN / 2;          // per-warp n extent
    constexpr int NF    = BNW / 8;         // n8 fragments per warp
    constexpr int SM_AH = 0;
    constexpr int SM_AL = 8192;
    constexpr int SM_BH = 16384;
    constexpr int SM_BL = SM_BH + BN * 64;

    __shared__ __align__(16) char smem[SM_BH + 2 * BN * 64];

    const int tid = threadIdx.x, lane = tid & 31, wid = tid >> 5;
    const int bm = blockIdx.y * 128;
    const int bn = blockIdx.x * BN;

    const float* A; const float* Bsrc; float* C;
    int lda, ldc;
    if (MODE == 0) {
        A = Ap + (size_t)bm * DM; lda = DM;
        Bsrc = Bp + (size_t)bn * DM;
        C = Cp; ldc = DM;
    } else {
        int bh = blockIdx.z; int b = bh >> 4; int h = bh & 15;
        A = Ap + (size_t)bh * SQ * SQ + (size_t)bm * SQ; lda = SQ;   // attn
        Bsrc = g_V + (size_t)b * SQ * DM + h * DK;                    // V (k-major rows)
        C = g_ctx + (size_t)b * SQ * DM + h * DK; ldc = DM;
    }

    const uint32_t sb  = smem_u32(smem);
    const uint32_t sAh = sb + SM_AH, sAl = sb + SM_AL;
    const uint32_t sBh = sb + SM_BH, sBl = sb + SM_BL;

    const int wm = (wid & 3) * 32;
    const int wn = (wid >> 2) * BNW;
    const int ar = lane & 15;
    const int ac = (lane >> 4) << 3;
    const int br = (lane & 7) + ((lane & 16) >> 1);
    const int bc = lane & 8;

    float c[2][NF][4];
    #pragma unroll
    for (int mi = 0; mi < 2; mi++)
        #pragma unroll
        for (int nf = 0; nf < NF; nf++)
            #pragma unroll
            for (int j = 0; j < 4; j++) c[mi][nf][j] = 0.f;

    float4 va[4], vb[4];

    // ---- initial prefetch (it = 0) ----
    #pragma unroll
    for (int i = 0; i < 4; i++) {
        int idx = tid + (i << 8);
        va[i] = *(const float4*)(A + (size_t)(idx >> 3) * lda + ((idx & 7) << 2));
    }
    if (MODE != 2) {
        #pragma unroll
        for (int i = 0; i < 4; i++) {
            int idx = tid + (i << 8);
            vb[i] = *(const float4*)(Bsrc + (size_t)(idx >> 3) * DM + ((idx & 7) << 2));
        }
    } else {
        #pragma unroll
        for (int i = 0; i < 2; i++) {
            int idx = tid + (i << 8);
            vb[i] = *(const float4*)(Bsrc + (size_t)(idx >> 4) * DM + ((idx & 15) << 2));
        }
    }

    for (int it = 0; it < NSTEP; ++it) {
        // ---- convert + STS from registers ----
        #pragma unroll
        for (int i = 0; i < 4; i++) {
            int idx = tid + (i << 8);
            int r = idx >> 3, c4 = (idx & 7) << 2;
            uint2 uh, ul; split4(va[i], uh, ul);
            uint32_t sw = swz64((uint32_t)(r * 64 + (c4 << 1)));
            *(uint2*)(smem + SM_AH + sw) = uh;
            *(uint2*)(smem + SM_AL + sw) = ul;
        }
        if (MODE != 2) {
            #pragma unroll
            for (int i = 0; i < 4; i++) {
                int idx = tid + (i << 8);
                int r = idx >> 3, c4 = (idx & 7) << 2;
                uint2 uh, ul; split4(vb[i], uh, ul);
                uint32_t sw = swz64((uint32_t)(r * 64 + (c4 << 1)));
                *(uint2*)(smem + SM_BH + sw) = uh;
                *(uint2*)(smem + SM_BL + sw) = ul;
            }
        } else {
            #pragma unroll
            for (int i = 0; i < 2; i++) {
                int idx = tid + (i << 8);
                int kr = idx >> 4, n4 = (idx & 15) << 2;
                float f[4] = {vb[i].x, vb[i].y, vb[i].z, vb[i].w};
                #pragma unroll
                for (int j = 0; j < 4; j++) {
                    __nv_bfloat16 hi = __float2bfloat16(f[j]);
                    __nv_bfloat16 lo = __float2bfloat16(f[j] - __bfloat162float(hi));
                    uint32_t sw = swz64((uint32_t)((n4 + j) * 64 + kr * 2));
                    *(__nv_bfloat16*)(smem + SM_BH + sw) = hi;
                    *(__nv_bfloat16*)(smem + SM_BL + sw) = lo;
                }
            }
        }
        __syncthreads();

        // ---- prefetch next tile into registers (lands during compute) ----
        if (it + 1 < NSTEP) {
            const int k0g = (it + 1) * 32;
            const float* srcA = A + k0g;
            #pragma unroll
            for (int i = 0; i < 4; i++) {
                int idx = tid + (i << 8);
                va[i] = *(const float4*)(srcA + (size_t)(idx >> 3) * lda + ((idx & 7) << 2));
            }
            if (MODE != 2) {
                const float* srcB = Bsrc + k0g;
                #pragma unroll
                for (int i = 0; i < 4; i++) {
                    int idx = tid + (i << 8);
                    vb[i] = *(const float4*)(srcB + (size_t)(idx >> 3) * DM + ((idx & 7) << 2));
                }
            } else {
                const float* srcB = Bsrc + (size_t)k0g * DM;
                #pragma unroll
                for (int i = 0; i < 2; i++) {
                    int idx = tid + (i << 8);
                    vb[i] = *(const float4*)(srcB + (size_t)(idx >> 4) * DM + ((idx & 15) << 2));
                }
            }
        }

        // ---- compute: 2 k16 steps; term-major MMA order ----
        #pragma unroll
        for (int ks = 0; ks < 2; ++ks) {
            uint32_t ah[2][4], al[2][4];
            #pragma unroll
            for (int mi = 0; mi < 2; mi++) {
                uint32_t off = swz64((uint32_t)((wm + mi * 16 + ar) * 64 + (ks * 16 + ac) * 2));
                LDMX4(ah[mi], sAh + off);
                LDMX4(al[mi], sAl + off);
            }
            #pragma unroll
            for (int p = 0; p < NF / 2; p++) {
                uint32_t bh[4], bl[4];
                uint32_t off = swz64((uint32_t)((wn + p * 16 + br) * 64 + (ks * 16 + bc) * 2));
                LDMX4(bh, sBh + off);
                LDMX4(bl, sBl + off);
                #pragma unroll
                for (int hh = 0; hh < 2; hh++)
                    #pragma unroll
                    for (int mi = 0; mi < 2; mi++)
                        MMA_BF16(c[mi][p * 2 + hh], ah[mi], bh[hh * 2], bh[hh * 2 + 1]);
                #pragma unroll
                for (int hh = 0; hh < 2; hh++)
                    #pragma unroll
                    for (int mi = 0; mi < 2; mi++)
                        MMA_BF16(c[mi][p * 2 + hh], ah[mi], bl[hh * 2], bl[hh * 2 + 1]);
                #pragma unroll
                for (int hh = 0; hh < 2; hh++)
                    #pragma unroll
                    for (int mi = 0; mi < 2; mi++)
                        MMA_BF16(c[mi][p * 2 + hh], al[mi], bh[hh * 2], bh[hh * 2 + 1]);
            }
        }
        __syncthreads();
    }

    // ---- epilogue ----
    #pragma unroll
    for (int mi = 0; mi < 2; mi++) {
        int row = bm + wm + mi * 16 + (lane >> 2);
        #pragma unroll
        for (int nf = 0; nf < NF; nf++) {
            int col = bn + wn + nf * 8 + ((lane & 3) << 1);
            *(float2*)(C + (size_t)row * ldc + col)       = make_float2(c[mi][nf][0], c[mi][nf][1]);
            *(float2*)(C + (size_t)(row + 8) * ldc + col) = make_float2(c[mi][nf][2], c[mi][nf][3]);
        }
    }
}

// ======================= fused qk + softmax =======================
// Per block: 128 q-rows of one (b,h) over all 2048 keys.
// S = QK^T/8 -> bitmap mask -> exp (no max: scores ~N(0,1)) -> write unnormalized,
// accumulate row sums -> renormalize own (L2-hot) slice.
#define FQ_QH 0
#define FQ_QL 16384
#define FQ_KH 32768
#define FQ_KL 49152
#define FQ_INV 65536
#define FQ_TOT (65536 + 512)

__global__ void __launch_bounds__(256, 2) fused_qk(float* __restrict__ attn_dst)
{
    extern __shared__ __align__(16) char smem[];
    const int tid = threadIdx.x, lane = tid & 31, wid = tid >> 5;
    const int qb = blockIdx.x;           // 0..15
    const int bh = blockIdx.y;           // 0..31
    const int b = bh >> 4, h = bh & 15;
    const int bm = qb * 128;

    const float* Qg = g_Q + ((size_t)b * SQ + bm) * DM + h * DK;
    const float* Kg = g_K + (size_t)b * SQ * DM + h * DK;
    float* attnp = attn_dst + (size_t)bh * SQ * SQ + (size_t)bm * SQ;
    const uint32_t* mbits = g_maskbits + ((size_t)b * SQ + bm) * (SQ / 32);

    const uint32_t sb = smem_u32(smem);
    const uint32_t sQh = sb + FQ_QH, sQl = sb + FQ_QL;
    const uint32_t sKh = sb + FQ_KH, sKl = sb + FQ_KL;
    float* sinv = (float*)(smem + FQ_INV);

    const int ar = lane & 15;
    const int ac = (lane >> 4) << 3;
    const int br = (lane & 7) + ((lane & 16) >> 1);
    const int bc = lane & 8;
    const int r0 = wid * 16 + (lane >> 2);   // local q row (and +8)

    // ---- load Q tile once: 128 rows x 64 d, hi/lo, SW128 ----
    #pragma unroll
    for (int i = 0; i < 8; i++) {
        int idx = tid + (i << 8);            // 2048 = 128 rows x 16 f4
        int r = idx >> 4, c4 = (idx & 15) << 2;
        float4 v = *(const float4*)(Qg + (size_t)r * DM + c4);
        uint2 uh, ul; split4(v, uh, ul);
        uint32_t sw = swz128((uint32_t)(r * 128 + c4 * 2));
        *(uint2*)(smem + FQ_QH + sw) = uh;
        *(uint2*)(smem + FQ_QL + sw) = ul;
    }

    float rsum0 = 0.f, rsum1 = 0.f;

    float4 vk[8];
    #pragma unroll
    for (int i = 0; i < 8; i++) {
        int idx = tid + (i << 8);
        vk[i] = *(const float4*)(Kg + (size_t)(idx >> 4) * DM + ((idx & 15) << 2));
    }

    for (int kb = 0; kb < 16; ++kb) {
        __syncthreads();   // previous compute done (and Q STS visible on kb=0)
        // ---- STS K tile from registers ----
        #pragma unroll
        for (int i = 0; i < 8; i++) {
            int idx = tid + (i << 8);
            int r = idx >> 4, c4 = (idx & 15) << 2;
            uint2 uh, ul; split4(vk[i], uh, ul);
            uint32_t sw = swz128((uint32_t)(r * 128 + c4 * 2));
            *(uint2*)(smem + FQ_KH + sw) = uh;
            *(uint2*)(smem + FQ_KL + sw) = ul;
        }
        __syncthreads();
        // ---- prefetch next K tile ----
        if (kb + 1 < 16) {
            const float* src = Kg + (size_t)(kb + 1) * 128 * DM;
            #pragma unroll
            for (int i = 0; i < 8; i++) {
                int idx = tid + (i << 8);
                vk[i] = *(const float4*)(src + (size_t)(idx >> 4) * DM + ((idx & 15) << 2));
            }
        }

        // ---- two 64-key halves: S, mask, exp, write ----
        #pragma unroll
        for (int half = 0; half < 2; ++half) {
            float c[8][4];
            #pragma unroll
            for (int nf = 0; nf < 8; nf++)
                #pragma unroll
                for (int j = 0; j < 4; j++) c[nf][j] = 0.f;

            #pragma unroll
            for (int ks = 0; ks < 4; ++ks) {
                uint32_t qh[4], ql[4];
                uint32_t qoff = swz128((uint32_t)((wid * 16 + ar) * 128 + (ks * 16 + ac) * 2));
                LDMX4(qh, sQh + qoff);
                LDMX4(ql, sQl + qoff);
                #pragma unroll
                for (int p = 0; p < 4; p++) {
                    uint32_t kh[4], kl[4];
                    uint32_t koff = swz128((uint32_t)((half * 64 + p * 16 + br) * 128 + (ks * 16 + bc) * 2));
                    LDMX4(kh, sKh + koff);
                    LDMX4(kl, sKl + koff);
                    #pragma unroll
                    for (int hh = 0; hh < 2; hh++)
                        MMA_BF16(c[p * 2 + hh], qh, kh[hh * 2], kh[hh * 2 + 1]);
                    #pragma unroll
                    for (int hh = 0; hh < 2; hh++)
                        MMA_BF16(c[p * 2 + hh], qh, kl[hh * 2], kl[hh * 2 + 1]);
                    #pragma unroll
                    for (int hh = 0; hh < 2; hh++)
                        MMA_BF16(c[p * 2 + hh], ql, kh[hh * 2], kh[hh * 2 + 1]);
                }
            }

            // mask + exp + row-sum + store unnormalized
            uint2 w0 = *(const uint2*)(mbits + (size_t)r0 * (SQ / 32) + kb * 4 + half * 2);
            uint2 w1 = *(const uint2*)(mbits + (size_t)(r0 + 8) * (SQ / 32) + kb * 4 + half * 2);
            #pragma unroll
            for (int nf = 0; nf < 8; nf++) {
                int lc = nf * 8 + ((lane & 3) << 1);       // 0..63
                uint32_t wa = (lc & 32) ? w0.y : w0.x;
                uint32_t wb = (lc & 32) ? w1.y : w1.x;
                int sh = lc & 31;
                float p0 = (wa >> sh) & 1       ? 0.f : __expf(0.125f * c[nf][0]);
                float p1 = (wa >> (sh + 1)) & 1 ? 0.f : __expf(0.125f * c[nf][1]);
                float p2 = (wb >> sh) & 1       ? 0.f : __expf(0.125f * c[nf][2]);
                float p3 = (wb >> (sh + 1)) & 1 ? 0.f : __expf(0.125f * c[nf][3]);
                rsum0 += p0 + p1; rsum1 += p2 + p3;
                int col = kb * 128 + half * 64 + lc;
                *(float2*)(attnp + (size_t)r0 * SQ + col)       = make_float2(p0, p1);
                *(float2*)(attnp + (size_t)(r0 + 8) * SQ + col) = make_float2(p2, p3);
            }
        }
    }

    // ---- reduce row sums across quad, publish inverse ----
    rsum0 += __shfl_xor_sync(0xffffffffu, rsum0, 1);
    rsum0 += __shfl_xor_sync(0xffffffffu, rsum0, 2);
    rsum1 += __shfl_xor_sync(0xffffffffu, rsum1, 1);
    rsum1 += __shfl_xor_sync(0xffffffffu, rsum1, 2);
    if ((lane & 3) == 0) { sinv[r0] = 1.0f / rsum0; sinv[r0 + 8] = 1.0f / rsum1; }
    __syncthreads();

    // ---- phase 2: normalize this block's attn slice (just-written, L2-hot) ----
    #pragma unroll 4
    for (int i = 0; i < 256; ++i) {
        int f4 = i * 256 + tid;              // 128 rows x 512 f4/row
        int row = f4 >> 9;
        float s = sinv[row];
        float4* ptr = (float4*)(attnp + (size_t)row * SQ) + (f4 & 511);
        float4 v = *ptr;
        v.x *= s; v.y *= s; v.z *= s; v.w *= s;
        *ptr = v;
    }
}

// ---------------- out = LayerNorm(fc + residual), one block per row of 1024 ---------
__global__ void __launch_bounds__(256) add_ln(const float* __restrict__ res, float* __restrict__ dst)
{
    const size_t row = blockIdx.x;
    const float* f = g_fc + row * DM;
    const float* r = res + row * DM;
    float* o = (dst ? dst : g_Q) + row * DM;
    const int tid = threadIdx.x, lane = tid & 31, warp = tid >> 5;
    __shared__ float sm[8];
    float x[4];
    float s = 0.f;
    #pragma unroll
    for (int i = 0; i < 4; i++) { x[i] = f[i * 256 + tid] + r[i * 256 + tid]; s += x[i]; }
    #pragma unroll
    for (int off = 16; off; off >>= 1) s += __shfl_xor_sync(0xffffffffu, s, off);
    if (lane == 0) sm[warp] = s;
    __syncthreads();
    s = sm[lane & 7];
    #pragma unroll
    for (int off = 4; off; off >>= 1) s += __shfl_xor_sync(0xffffffffu, s, off);
    const float mean = s * (1.0f / DM);
    float s2 = 0.f;
    #pragma unroll
    for (int i = 0; i < 4; i++) { float d = x[i] - mean; s2 += d * d; }
    #pragma unroll
    for (int off = 16; off; off >>= 1) s2 += __shfl_xor_sync(0xffffffffu, s2, off);
    __syncthreads();
    if (lane == 0) sm[warp] = s2;
    __syncthreads();
    s2 = sm[lane & 7];
    #pragma unroll
    for (int off = 4; off; off >>= 1) s2 += __shfl_xor_sync(0xffffffffu, s2, off);
    const float inv = rsqrtf(s2 * (1.0f / DM) + 1e-5f);
    #pragma unroll
    for (int i = 0; i < 4; i++) o[i * 256 + tid] = (x[i] - mean) * inv;
}

// ---------------- launch -----------------------------------------------------------
extern "C" void kernel_launch(void* const* d_in, const int* in_sizes, int n_in,
                              void* d_out, int out_size)
{
    const float* iQ  = (const float*)d_in[0];
    const float* iK  = (const float*)d_in[1];
    const float* iV  = (const float*)d_in[2];
    const void*  msk = d_in[3];
    const float* WQ  = (const float*)d_in[4];
    const float* WK  = (const float*)d_in[5];
    const float* WV  = (const float*)d_in[6];
    const float* Wfc = (const float*)d_in[7];
    float* out = (float*)d_out;

    const long long LN_N  = (long long)ROWS * DM;        // 4,194,304
    const long long ATT_N = (long long)BHN * SQ * SQ;    // 134,217,728
    float* attn_out = nullptr;
    float* ln_out   = out;
    if ((long long)out_size >= LN_N + ATT_N) {
        attn_out = out + LN_N;
    } else if ((long long)out_size == ATT_N) {
        attn_out = out;
        ln_out = nullptr;
    }

    void* p;
    cudaGetSymbolAddress(&p, g_Q);    float* pQ    = (float*)p;
    cudaGetSymbolAddress(&p, g_K);    float* pK    = (float*)p;
    cudaGetSymbolAddress(&p, g_V);    float* pV    = (float*)p;
    cudaGetSymbolAddress(&p, g_ctx);  float* pCtx  = (float*)p;
    cudaGetSymbolAddress(&p, g_fc);   float* pFc   = (float*)p;
    cudaGetSymbolAddress(&p, g_attn); float* pAttn = (float*)p;

    static int smem_set = 0;
    if (!smem_set) {
        cudaFuncSetAttribute(fused_qk, cudaFuncAttributeMaxDynamicSharedMemorySize, FQ_TOT);
        smem_set = 1;
    }

    detect_mask_kernel<<<1, 256>>>(msk);
    mask_to_bits<<<(BB * SQ * SQ / 32) / 8, 256>>>(msk);

    dim3 gp(DM / 128, ROWS / 128);               // (8, 32)
    mma_gemm<0><<<gp, 256>>>(iQ, WQ, pQ);
    mma_gemm<0><<<gp, 256>>>(iK, WK, pK);
    mma_gemm<0><<<gp, 256>>>(iV, WV, pV);

    float* attn_dst = attn_out ? attn_out : pAttn;
    dim3 ga(SQ / 128, BHN);                      // (16, 32)
    fused_qk<<<ga, 256, FQ_TOT>>>(attn_dst);

    dim3 gv(1, SQ / 128, BHN);                   // (1, 16, 32)
    mma_gemm<2><<<gv, 256>>>(attn_dst, nullptr, nullptr);

    mma_gemm<0><<<gp, 256>>>(pCtx, Wfc, pFc);

    add_ln<<<(unsigned)ROWS, 256>>>(iQ, ln_out);
}

// round 14
// speedup vs baseline: 1.1627x; 1.1627x over previous
#include <cuda_runtime.h>
#include <cuda_bf16.h>
#include <math.h>
#include <stdint.h>

// Problem dims
#define SQ   2048
#define DM   1024
#define NH   16
#define DK   64
#define BB   2
#define ROWS (BB*SQ)   // 4096
#define BHN  (BB*NH)   // 32

// ---------------- scratch (static device memory; no allocs allowed) ----------------
// split-bf16 operand arrays (hi/lo)
__device__ __nv_bfloat16 g_inQh[(size_t)ROWS*DM], g_inQl[(size_t)ROWS*DM];
__device__ __nv_bfloat16 g_inKh[(size_t)ROWS*DM], g_inKl[(size_t)ROWS*DM];
__device__ __nv_bfloat16 g_inVh[(size_t)ROWS*DM], g_inVl[(size_t)ROWS*DM];
__device__ __nv_bfloat16 g_Wqh[(size_t)DM*DM], g_Wql[(size_t)DM*DM];
__device__ __nv_bfloat16 g_Wkh[(size_t)DM*DM], g_Wkl[(size_t)DM*DM];
__device__ __nv_bfloat16 g_Wvh[(size_t)DM*DM], g_Wvl[(size_t)DM*DM];
__device__ __nv_bfloat16 g_Wfh[(size_t)DM*DM], g_Wfl[(size_t)DM*DM];
__device__ __nv_bfloat16 g_Qh[(size_t)ROWS*DM], g_Ql[(size_t)ROWS*DM];
__device__ __nv_bfloat16 g_Kh[(size_t)ROWS*DM], g_Kl[(size_t)ROWS*DM];
__device__ __nv_bfloat16 g_Vh[(size_t)ROWS*DM], g_Vl[(size_t)ROWS*DM];
__device__ __nv_bfloat16 g_ctxh[(size_t)ROWS*DM], g_ctxl[(size_t)ROWS*DM];
__device__ float g_fc [ (size_t)ROWS*DM ];
__device__ float g_attn[ (size_t)BHN*SQ*SQ ];            // attn dump when not in d_out
__device__ uint32_t g_maskbits[ (size_t)BB*SQ*SQ/32 ];   // 1 bit per (b,q,k)
__device__ int   g_maskmode;

// ---------------- mask dtype detection ----------------
__global__ void detect_mask_kernel(const void* __restrict__ mask)
{
    __shared__ int ok[3];
    int tid = threadIdx.x;
    if (tid < 3) ok[tid] = 1;
    __syncthreads();
    const unsigned int*   pi = (const unsigned int*)mask;
    const unsigned short* ps = (const unsigned short*)mask;
    bool i32ok = true, f32ok = true, bfok = true;
    for (int i = tid; i < 4096; i += 256) {
        unsigned int v = pi[i];
        if (v > 1u) i32ok = false;
        if (v != 0u && v != 0x3F800000u) f32ok = false;
    }
    for (int i = tid; i < 4096; i += 256) {
        unsigned short v = ps[i];
        if (v != 0 && v != 0x3F80) bfok = false;
    }
    if (!i32ok) atomicAnd(&ok[0], 0);
    if (!f32ok) atomicAnd(&ok[1], 0);
    if (!bfok)  atomicAnd(&ok[2], 0);
    __syncthreads();
    if (tid == 0)
        g_maskmode = ok[0] ? 0 : (ok[1] ? 1 : (ok[2] ? 3 : 2));
}

__device__ __forceinline__ bool mask_at(const void* __restrict__ mask, size_t idx, int mode)
{
    if (mode == 0) return ((const int*)mask)[idx] != 0;
    if (mode == 1) return ((const float*)mask)[idx] != 0.0f;
    if (mode == 2) return ((const unsigned char*)mask)[idx] != 0;
    return ((const unsigned short*)mask)[idx] != 0;
}

// mask -> bitmap: one warp per 32-bit word, ballot
__global__ void __launch_bounds__(256) mask_to_bits(const void* __restrict__ mask)
{
    const int w = blockIdx.x * 8 + (threadIdx.x >> 5);
    const int lane = threadIdx.x & 31;
    const int mode = g_maskmode;
    size_t idx = (size_t)w * 32 + lane;
    bool m = mask_at(mask, idx, mode);
    uint32_t bits = __ballot_sync(0xffffffffu, m);
    if (lane == 0) g_maskbits[w] = bits;
}

// ======================= helpers =======================
__device__ __forceinline__ uint32_t smem_u32(const void* p) {
    uint32_t a;
    asm("{ .reg .u64 t; cvta.to.shared.u64 t, %1; cvt.u32.u64 %0, t; }" : "=r"(a) : "l"(p));
    return a;
}
__device__ __forceinline__ uint32_t swz64(uint32_t b)  { return b ^ ((b >> 3) & 0x30); }

// split f32 -> bf16 hi + bf16 lo
__device__ __forceinline__ void split4(float4 v, uint2& uh, uint2& ul)
{
    __nv_bfloat16 hx = __float2bfloat16(v.x), hy = __float2bfloat16(v.y);
    __nv_bfloat16 hz = __float2bfloat16(v.z), hw = __float2bfloat16(v.w);
    __nv_bfloat16 lx = __float2bfloat16(v.x - __bfloat162float(hx));
    __nv_bfloat16 ly = __float2bfloat16(v.y - __bfloat162float(hy));
    __nv_bfloat16 lz = __float2bfloat16(v.z - __bfloat162float(hz));
    __nv_bfloat16 lw = __float2bfloat16(v.w - __bfloat162float(hw));
    union { __nv_bfloat162 b2[2]; uint2 u; } th, tl;
    th.b2[0] = __halves2bfloat162(hx, hy); th.b2[1] = __halves2bfloat162(hz, hw);
    tl.b2[0] = __halves2bfloat162(lx, ly); tl.b2[1] = __halves2bfloat162(lz, lw);
    uh = th.u; ul = tl.u;
}

// streaming f32 -> split bf16 (hi/lo) converter
__global__ void __launch_bounds__(256) convert_split(const float4* __restrict__ src,
                                                     uint2* __restrict__ hi,
                                                     uint2* __restrict__ lo, int n4)
{
    int i = blockIdx.x * 256 + threadIdx.x;
    const int stride = gridDim.x * 256;
    for (; i < n4; i += stride) {
        uint2 uh, ul; split4(src[i], uh, ul);
        hi[i] = uh; lo[i] = ul;
    }
}

#define LDMX4(r, addr) \
    asm volatile("ldmatrix.sync.aligned.m8n8.x4.shared.b16 {%0,%1,%2,%3}, [%4];" \
        : "=r"((r)[0]), "=r"((r)[1]), "=r"((r)[2]), "=r"((r)[3]) : "r"(addr))

#define MMA_BF16(cc, a, b0_, b1_) \
    asm volatile("mma.sync.aligned.m16n8k16.row.col.f32.bf16.bf16.f32 " \
        "{%0,%1,%2,%3}, {%4,%5,%6,%7}, {%8,%9}, {%0,%1,%2,%3};" \
        : "+f"((cc)[0]), "+f"((cc)[1]), "+f"((cc)[2]), "+f"((cc)[3]) \
        : "r"((a)[0]), "r"((a)[1]), "r"((a)[2]), "r"((a)[3]), "r"(b0_), "r"(b1_))

// ======================= bf16x3 mma.sync GEMM, pre-split operands =======================
// MODE 0: dense  C[4096,1024] = A * B^T ; A,B pre-split bf16. OUTBF: 1 -> split bf16 out, 0 -> f32 out
// MODE 1: qk     per bh: scores = mask ? -1e9 : (Q K^T)/8 -> f32 Cf  (bitmap mask)
// MODE 2: pv     per bh: ctx = attn(f32)[2048,2048] @ V(bf16)[2048,64] -> split bf16 ctx
template<int MODE, int OUTBF>
__global__ void __launch_bounds__(256, 2) mma_gemm(
    const float* __restrict__ Af,
    const __nv_bfloat16* __restrict__ Ah_, const __nv_bfloat16* __restrict__ Al_,
    const __nv_bfloat16* __restrict__ Bh_, const __nv_bfloat16* __restrict__ Bl_,
    float* __restrict__ Cf,
    __nv_bfloat16* __restrict__ Ch_, __nv_bfloat16* __restrict__ Cl_)
{
    constexpr int BN    = (MODE == 2) ? 64 : 128;
    constexpr int NSTEP = (MODE == 0) ? 32 : ((MODE == 1) ? 2 : 64);
    constexpr int BNW   = BN / 2;          // per-warp n extent
    constexpr int NF    = BNW / 8;         // n8 fragments per warp
    constexpr int SM_AH = 0;
    constexpr int SM_AL = 8192;
    constexpr int SM_BH = 16384;
    constexpr int SM_BL = SM_BH + BN * 64;

    __shared__ __align__(16) char smem[SM_BH + 2 * BN * 64];

    const int tid = threadIdx.x, lane = tid & 31, wid = tid >> 5;
    const int bm = blockIdx.y * 128;
    const int bn = blockIdx.x * BN;

    int b = 0, h = 0;
    const __nv_bfloat16 *Ah = nullptr, *Al = nullptr, *Bh = nullptr, *Bl = nullptr;
    const float* Afp = nullptr;
    float* Cfp = nullptr;
    size_t lda = DM;

    if (MODE == 0) {
        Ah = Ah_ + (size_t)bm * DM; Al = Al_ + (size_t)bm * DM;
        Bh = Bh_ + (size_t)bn * DM; Bl = Bl_ + (size_t)bn * DM;
        Cfp = Cf;
    } else if (MODE == 1) {
        int bh = blockIdx.z; b = bh >> 4; h = bh & 15;
        Ah = g_Qh + ((size_t)b * SQ + bm) * DM + h * DK;
        Al = g_Ql + ((size_t)b * SQ + bm) * DM + h * DK;
        Bh = g_Kh + ((size_t)b * SQ + bn) * DM + h * DK;
        Bl = g_Kl + ((size_t)b * SQ + bn) * DM + h * DK;
        Cfp = Cf + (size_t)bh * SQ * SQ;
    } else {
        int bh = blockIdx.z; b = bh >> 4; h = bh & 15;
        Afp = Af + (size_t)bh * SQ * SQ + (size_t)bm * SQ;
        Bh = g_Vh + (size_t)b * SQ * DM + h * DK;
        Bl = g_Vl + (size_t)b * SQ * DM + h * DK;
    }

    const uint32_t sb  = smem_u32(smem);
    const uint32_t sAh = sb + SM_AH, sAl = sb + SM_AL;
    const uint32_t sBh = sb + SM_BH, sBl = sb + SM_BL;

    const int wm = (wid & 3) * 32;
    const int wn = (wid >> 2) * BNW;
    const int ar = lane & 15;
    const int ac = (lane >> 4) << 3;
    const int br = (lane & 7) + ((lane & 16) >> 1);
    const int bc = lane & 8;

    float c[2][NF][4];
    #pragma unroll
    for (int mi = 0; mi < 2; mi++)
        #pragma unroll
        for (int nf = 0; nf < NF; nf++)
            #pragma unroll
            for (int j = 0; j < 4; j++) c[mi][nf][j] = 0.f;

    for (int it = 0; it < NSTEP; ++it) {
        const int k0 = it * 32;
        __syncthreads();   // previous chunk's compute done before overwrite

        // ---- A tile: 128 rows x 32 k ----
        if (MODE != 2) {
            // pure bf16 copy: 512 16B chunks per array, 2/thread
            #pragma unroll
            for (int i = 0; i < 2; i++) {
                int idx = tid + (i << 8);
                int r = idx >> 2, c16 = (idx & 3) << 4;
                size_t go = ((size_t)r * lda + k0) * 2 + c16;
                uint4 vh = *(const uint4*)((const char*)Ah + go);
                uint4 vl = *(const uint4*)((const char*)Al + go);
                uint32_t sw = swz64((uint32_t)(r * 64 + c16));
                *(uint4*)(smem + SM_AH + sw) = vh;
                *(uint4*)(smem + SM_AL + sw) = vl;
            }
        } else {
            // attn f32 -> split in-kernel (4 f4/thread)
            const float* src = Afp + k0;
            #pragma unroll
            for (int i = 0; i < 4; i++) {
                int idx = tid + (i << 8);
                int r = idx >> 3, c4 = (idx & 7) << 2;
                float4 v = *(const float4*)(src + (size_t)r * SQ + c4);
                uint2 uh, ul; split4(v, uh, ul);
                uint32_t sw = swz64((uint32_t)(r * 64 + (c4 << 1)));
                *(uint2*)(smem + SM_AH + sw) = uh;
                *(uint2*)(smem + SM_AL + sw) = ul;
            }
        }
        // ---- B tile ----
        if (MODE != 2) {
            #pragma unroll
            for (int i = 0; i < 2; i++) {
                int idx = tid + (i << 8);
                int r = idx >> 2, c16 = (idx & 3) << 4;
                size_t go = ((size_t)r * DM + k0) * 2 + c16;
                uint4 vh = *(const uint4*)((const char*)Bh + go);
                uint4 vl = *(const uint4*)((const char*)Bl + go);
                uint32_t sw = swz64((uint32_t)(r * 64 + c16));
                *(uint4*)(smem + SM_BH + sw) = vh;
                *(uint4*)(smem + SM_BL + sw) = vl;
            }
        } else {
            // transpose-copy V: Bs[n][k] = V[k0+kr][n]; 1 chunk (8 n) per thread per array
            int kr = tid >> 3, n8 = (tid & 7) << 3;
            size_t go = ((size_t)(k0 + kr) * DM + n8) * 2;
            uint4 vh = *(const uint4*)((const char*)Bh + go);
            uint4 vl = *(const uint4*)((const char*)Bl + go);
            const __nv_bfloat16* ph = (const __nv_bfloat16*)&vh;
            const __nv_bfloat16* pl = (const __nv_bfloat16*)&vl;
            #pragma unroll
            for (int j = 0; j < 8; j++) {
                uint32_t sw = swz64((uint32_t)((n8 + j) * 64 + kr * 2));
                *(__nv_bfloat16*)(smem + SM_BH + sw) = ph[j];
                *(__nv_bfloat16*)(smem + SM_BL + sw) = pl[j];
            }
        }
        __syncthreads();

        // ---- compute: 2 k16 steps; term-major MMA order ----
        #pragma unroll
        for (int ks = 0; ks < 2; ++ks) {
            uint32_t ah[2][4], al[2][4];
            #pragma unroll
            for (int mi = 0; mi < 2; mi++) {
                uint32_t off = swz64((uint32_t)((wm + mi * 16 + ar) * 64 + (ks * 16 + ac) * 2));
                LDMX4(ah[mi], sAh + off);
                LDMX4(al[mi], sAl + off);
            }
            #pragma unroll
            for (int p = 0; p < NF / 2; p++) {
                uint32_t bh4[4], bl4[4];
                uint32_t off = swz64((uint32_t)((wn + p * 16 + br) * 64 + (ks * 16 + bc) * 2));
                LDMX4(bh4, sBh + off);
                LDMX4(bl4, sBl + off);
                #pragma unroll
                for (int hh = 0; hh < 2; hh++)
                    #pragma unroll
                    for (int mi = 0; mi < 2; mi++)
                        MMA_BF16(c[mi][p * 2 + hh], ah[mi], bh4[hh * 2], bh4[hh * 2 + 1]);
                #pragma unroll
                for (int hh = 0; hh < 2; hh++)
                    #pragma unroll
                    for (int mi = 0; mi < 2; mi++)
                        MMA_BF16(c[mi][p * 2 + hh], ah[mi], bl4[hh * 2], bl4[hh * 2 + 1]);
                #pragma unroll
                for (int hh = 0; hh < 2; hh++)
                    #pragma unroll
                    for (int mi = 0; mi < 2; mi++)
                        MMA_BF16(c[mi][p * 2 + hh], al[mi], bh4[hh * 2], bh4[hh * 2 + 1]);
            }
        }
    }

    // ---- epilogue ----
    #pragma unroll
    for (int mi = 0; mi < 2; mi++) {
        int row = bm + wm + mi * 16 + (lane >> 2);
        uint2 wa, wb;
        if (MODE == 1) {
            const uint32_t* mr = g_maskbits + ((size_t)b * SQ + row) * (SQ / 32) + ((bn + wn) >> 5);
            wa = *(const uint2*)mr;
            wb = *(const uint2*)(mr + 8 * (SQ / 32));
        }
        #pragma unroll
        for (int nf = 0; nf < NF; nf++) {
            int lc = nf * 8 + ((lane & 3) << 1);
            float2 v0 = make_float2(c[mi][nf][0], c[mi][nf][1]);
            float2 v1 = make_float2(c[mi][nf][2], c[mi][nf][3]);
            if (MODE == 1) {
                uint32_t w0 = (lc & 32) ? wa.y : wa.x;
                uint32_t w1 = (lc & 32) ? wb.y : wb.x;
                int sh = lc & 31;
                v0.x = (w0 >> sh) & 1       ? -1e9f : v0.x * 0.125f;
                v0.y = (w0 >> (sh + 1)) & 1 ? -1e9f : v0.y * 0.125f;
                v1.x = (w1 >> sh) & 1       ? -1e9f : v1.x * 0.125f;
                v1.y = (w1 >> (sh + 1)) & 1 ? -1e9f : v1.y * 0.125f;
                int col = bn + wn + lc;
                *(float2*)(Cfp + (size_t)row * SQ + col)       = v0;
                *(float2*)(Cfp + (size_t)(row + 8) * SQ + col) = v1;
            } else if (MODE == 0 && !OUTBF) {
                int col = bn + wn + lc;
                *(float2*)(Cfp + (size_t)row * DM + col)       = v0;
                *(float2*)(Cfp + (size_t)(row + 8) * DM + col) = v1;
            } else {
                // split-bf16 output (projections / ctx)
                size_t o0, o1;
                if (MODE == 0) {
                    int col = bn + wn + lc;
                    o0 = (size_t)row * DM + col;
                    o1 = (size_t)(row + 8) * DM + col;
                } else {
                    int col = wn + lc;   // bn = 0, head-local
                    o0 = ((size_t)b * SQ + row) * DM + h * DK + col;
                    o1 = ((size_t)b * SQ + row + 8) * DM + h * DK + col;
                }
                __nv_bfloat16* Ch = (MODE == 0) ? Ch_ : g_ctxh;
                __nv_bfloat16* Cl = (MODE == 0) ? Cl_ : g_ctxl;
                __nv_bfloat16 h0 = __float2bfloat16(v0.x), h1 = __float2bfloat16(v0.y);
                __nv_bfloat16 h2 = __float2bfloat16(v1.x), h3 = __float2bfloat16(v1.y);
                *(__nv_bfloat162*)(Ch + o0) = __halves2bfloat162(h0, h1);
                *(__nv_bfloat162*)(Ch + o1) = __halves2bfloat162(h2, h3);
                *(__nv_bfloat162*)(Cl + o0) = __halves2bfloat162(
                    __float2bfloat16(v0.x - __bfloat162float(h0)),
                    __float2bfloat16(v0.y - __bfloat162float(h1)));
                *(__nv_bfloat162*)(Cl + o1) = __halves2bfloat162(
                    __float2bfloat16(v1.x - __bfloat162float(h2)),
                    __float2bfloat16(v1.y - __bfloat162float(h3)));
            }
        }
    }
}

// ---------------- row softmax over 2048, one block per row --------------------------
__global__ void __launch_bounds__(256) softmax_rows(const float* __restrict__ src,
                                                    float* __restrict__ dst)
{
    const size_t row = blockIdx.x;
    const float* x = src + row * SQ;
    float* y = dst + row * SQ;
    const int tid = threadIdx.x, lane = tid & 31, warp = tid >> 5;
    __shared__ float sm[8];
    float v[8];
    float m = -3.0e38f;
    #pragma unroll
    for (int i = 0; i < 8; i++) { v[i] = x[i * 256 + tid]; m = fmaxf(m, v[i]); }
    #pragma unroll
    for (int o = 16; o; o >>= 1) m = fmaxf(m, __shfl_xor_sync(0xffffffffu, m, o));
    if (lane == 0) sm[warp] = m;
    __syncthreads();
    m = sm[lane & 7];
    #pragma unroll
    for (int o = 4; o; o >>= 1) m = fmaxf(m, __shfl_xor_sync(0xffffffffu, m, o));
    float s = 0.f;
    #pragma unroll
    for (int i = 0; i < 8; i++) { v[i] = expf(v[i] - m); s += v[i]; }
    #pragma unroll
    for (int o = 16; o; o >>= 1) s += __shfl_xor_sync(0xffffffffu, s, o);
    __syncthreads();
    if (lane == 0) sm[warp] = s;
    __syncthreads();
    s = sm[lane & 7];
    #pragma unroll
    for (int o = 4; o; o >>= 1) s += __shfl_xor_sync(0xffffffffu, s, o);
    const float inv = 1.0f / s;
    #pragma unroll
    for (int i = 0; i < 8; i++) y[i * 256 + tid] = v[i] * inv;
}

// ---------------- out = LayerNorm(fc + residual), one block per row of 1024 ---------
__global__ void __launch_bounds__(256) add_ln(const float* __restrict__ res, float* __restrict__ dst)
{
    const size_t row = blockIdx.x;
    const float* f = g_fc + row * DM;
    const float* r = res + row * DM;
    float* o = dst + row * DM;
    const int tid = threadIdx.x, lane = tid & 31, warp = tid >> 5;
    __shared__ float sm[8];
    float x[4];
    float s = 0.f;
    #pragma unroll
    for (int i = 0; i < 4; i++) { x[i] = f[i * 256 + tid] + r[i * 256 + tid]; s += x[i]; }
    #pragma unroll
    for (int off = 16; off; off >>= 1) s += __shfl_xor_sync(0xffffffffu, s, off);
    if (lane == 0) sm[warp] = s;
    __syncthreads();
    s = sm[lane & 7];
    #pragma unroll
    for (int off = 4; off; off >>= 1) s += __shfl_xor_sync(0xffffffffu, s, off);
    const float mean = s * (1.0f / DM);
    float s2 = 0.f;
    #pragma unroll
    for (int i = 0; i < 4; i++) { float d = x[i] - mean; s2 += d * d; }
    #pragma unroll
    for (int off = 16; off; off >>= 1) s2 += __shfl_xor_sync(0xffffffffu, s2, off);
    __syncthreads();
    if (lane == 0) sm[warp] = s2;
    __syncthreads();
    s2 = sm[lane & 7];
    #pragma unroll
    for (int off = 4; off; off >>= 1) s2 += __shfl_xor_sync(0xffffffffu, s2, off);
    const float inv = rsqrtf(s2 * (1.0f / DM) + 1e-5f);
    #pragma unroll
    for (int i = 0; i < 4; i++) o[i * 256 + tid] = (x[i] - mean) * inv;
}

// ---------------- launch -----------------------------------------------------------
extern "C" void kernel_launch(void* const* d_in, const int* in_sizes, int n_in,
                              void* d_out, int out_size)
{
    const float* iQ  = (const float*)d_in[0];
    const float* iK  = (const float*)d_in[1];
    const float* iV  = (const float*)d_in[2];
    const void*  msk = d_in[3];
    const float* WQ  = (const float*)d_in[4];
    const float* WK  = (const float*)d_in[5];
    const float* WV  = (const float*)d_in[6];
    const float* Wfc = (const float*)d_in[7];
    float* out = (float*)d_out;

    const long long LN_N  = (long long)ROWS * DM;        // 4,194,304
    const long long ATT_N = (long long)BHN * SQ * SQ;    // 134,217,728
    float* attn_out = nullptr;
    float* ln_out   = out;
    if ((long long)out_size >= LN_N + ATT_N) {
        attn_out = out + LN_N;
    } else if ((long long)out_size == ATT_N) {
        attn_out = out;
        ln_out = nullptr;
    }

    void* p;
    cudaGetSymbolAddress(&p, g_attn); float* pAttn = (float*)p;
    cudaGetSymbolAddress(&p, g_fc);   float* pFc   = (float*)p;
    __nv_bfloat16 *inQh, *inQl, *inKh, *inKl, *inVh, *inVl;
    __nv_bfloat16 *wqh, *wql, *wkh, *wkl, *wvh, *wvl, *wfh, *wfl;
    __nv_bfloat16 *qh, *ql, *kh, *kl, *vh, *vl, *cth, *ctl;
    cudaGetSymbolAddress(&p, g_inQh); inQh = (__nv_bfloat16*)p;
    cudaGetSymbolAddress(&p, g_inQl); inQl = (__nv_bfloat16*)p;
    cudaGetSymbolAddress(&p, g_inKh); inKh = (__nv_bfloat16*)p;
    cudaGetSymbolAddress(&p, g_inKl); inKl = (__nv_bfloat16*)p;
    cudaGetSymbolAddress(&p, g_inVh); inVh = (__nv_bfloat16*)p;
    cudaGetSymbolAddress(&p, g_inVl); inVl = (__nv_bfloat16*)p;
    cudaGetSymbolAddress(&p, g_Wqh);  wqh = (__nv_bfloat16*)p;
    cudaGetSymbolAddress(&p, g_Wql);  wql = (__nv_bfloat16*)p;
    cudaGetSymbolAddress(&p, g_Wkh);  wkh = (__nv_bfloat16*)p;
    cudaGetSymbolAddress(&p, g_Wkl);  wkl = (__nv_bfloat16*)p;
    cudaGetSymbolAddress(&p, g_Wvh);  wvh = (__nv_bfloat16*)p;
    cudaGetSymbolAddress(&p, g_Wvl);  wvl = (__nv_bfloat16*)p;
    cudaGetSymbolAddress(&p, g_Wfh);  wfh = (__nv_bfloat16*)p;
    cudaGetSymbolAddress(&p, g_Wfl);  wfl = (__nv_bfloat16*)p;
    cudaGetSymbolAddress(&p, g_Qh);   qh  = (__nv_bfloat16*)p;
    cudaGetSymbolAddress(&p, g_Ql);   ql  = (__nv_bfloat16*)p;
    cudaGetSymbolAddress(&p, g_Kh);   kh  = (__nv_bfloat16*)p;
    cudaGetSymbolAddress(&p, g_Kl);   kl  = (__nv_bfloat16*)p;
    cudaGetSymbolAddress(&p, g_Vh);   vh  = (__nv_bfloat16*)p;
    cudaGetSymbolAddress(&p, g_Vl);   vl  = (__nv_bfloat16*)p;
    cudaGetSymbolAddress(&p, g_ctxh); cth = (__nv_bfloat16*)p;
    cudaGetSymbolAddress(&p, g_ctxl); ctl = (__nv_bfloat16*)p;

    detect_mask_kernel<<<1, 256>>>(msk);
    mask_to_bits<<<(BB * SQ * SQ / 32) / 8, 256>>>(msk);

    // pre-split inputs and weights to bf16 hi/lo
    const int NIN4 = ROWS * DM / 4, NW4 = DM * DM / 4;
    convert_split<<<1024, 256>>>((const float4*)iQ,  (uint2*)inQh, (uint2*)inQl, NIN4);
    convert_split<<<1024, 256>>>((const float4*)iK,  (uint2*)inKh, (uint2*)inKl, NIN4);
    convert_split<<<1024, 256>>>((const float4*)iV,  (uint2*)inVh, (uint2*)inVl, NIN4);
    convert_split<<<512,  256>>>((const float4*)WQ,  (uint2*)wqh,  (uint2*)wql,  NW4);
    convert_split<<<512,  256>>>((const float4*)WK,  (uint2*)wkh,  (uint2*)wkl,  NW4);
    convert_split<<<512,  256>>>((const float4*)WV,  (uint2*)wvh,  (uint2*)wvl,  NW4);
    convert_split<<<512,  256>>>((const float4*)Wfc, (uint2*)wfh,  (uint2*)wfl,  NW4);

    // projections: bf16 in, split-bf16 out
    dim3 gp(DM / 128, ROWS / 128);               // (8, 32)
    mma_gemm<0,1><<<gp, 256>>>(nullptr, inQh, inQl, wqh, wql, nullptr, qh, ql);
    mma_gemm<0,1><<<gp, 256>>>(nullptr, inKh, inKl, wkh, wkl, nullptr, kh, kl);
    mma_gemm<0,1><<<gp, 256>>>(nullptr, inVh, inVl, wvh, wvl, nullptr, vh, vl);

    // qk scores -> g_attn scratch
    dim3 gs(SQ / 128, SQ / 128, BHN);            // (16, 16, 32)
    mma_gemm<1,0><<<gs, 256>>>(nullptr, nullptr, nullptr, nullptr, nullptr, pAttn, nullptr, nullptr);

    float* attn_dst = attn_out ? attn_out : pAttn;
    softmax_rows<<<(unsigned)(BHN * SQ), 256>>>(pAttn, attn_dst);

    // pv: attn f32 + V bf16 -> ctx split bf16
    dim3 gv(1, SQ / 128, BHN);                   // (1, 16, 32)
    mma_gemm<2,1><<<gv, 256>>>(attn_dst, nullptr, nullptr, nullptr, nullptr, nullptr, nullptr, nullptr);

    // fc: ctx bf16 @ Wfc bf16 -> f32
    mma_gemm<0,0><<<gp, 256>>>(nullptr, cth, ctl, wfh, wfl, pFc, nullptr, nullptr);

    add_ln<<<(unsigned)ROWS, 256>>>(iQ, ln_out);
}

// round 15
// speedup vs baseline: 1.2500x; 1.0750x over previous
#include <cuda_runtime.h>
#include <cuda_bf16.h>
#include <math.h>
#include <stdint.h>

// Problem dims
#define SQ   2048
#define DM   1024
#define NH   16
#define DK   64
#define BB   2
#define ROWS (BB*SQ)   // 4096
#define BHN  (BB*NH)   // 32

// ---------------- scratch (static device memory; no allocs allowed) ----------------
__device__ __nv_bfloat16 g_inQh[(size_t)ROWS*DM], g_inQl[(size_t)ROWS*DM];
__device__ __nv_bfloat16 g_inKh[(size_t)ROWS*DM], g_inKl[(size_t)ROWS*DM];
__device__ __nv_bfloat16 g_inVh[(size_t)ROWS*DM], g_inVl[(size_t)ROWS*DM];
__device__ __nv_bfloat16 g_Wqh[(size_t)DM*DM], g_Wql[(size_t)DM*DM];
__device__ __nv_bfloat16 g_Wkh[(size_t)DM*DM], g_Wkl[(size_t)DM*DM];
__device__ __nv_bfloat16 g_Wvh[(size_t)DM*DM], g_Wvl[(size_t)DM*DM];
__device__ __nv_bfloat16 g_Wfh[(size_t)DM*DM], g_Wfl[(size_t)DM*DM];
__device__ __nv_bfloat16 g_Qh[(size_t)ROWS*DM], g_Ql[(size_t)ROWS*DM];
__device__ __nv_bfloat16 g_Kh[(size_t)ROWS*DM], g_Kl[(size_t)ROWS*DM];
__device__ __nv_bfloat16 g_Vh[(size_t)ROWS*DM], g_Vl[(size_t)ROWS*DM];
__device__ __nv_bfloat16 g_ctxh[(size_t)ROWS*DM], g_ctxl[(size_t)ROWS*DM];
__device__ float g_fc [ (size_t)ROWS*DM ];
__device__ float g_attn[ (size_t)BHN*SQ*SQ ];            // attn dump when not in d_out
__device__ uint32_t g_maskbits[ (size_t)BB*SQ*SQ/32 ];   // 1 bit per (b,q,k)
__device__ int   g_maskmode;

// ---------------- mask dtype detection ----------------
__global__ void detect_mask_kernel(const void* __restrict__ mask)
{
    __shared__ int ok[3];
    int tid = threadIdx.x;
    if (tid < 3) ok[tid] = 1;
    __syncthreads();
    const unsigned int*   pi = (const unsigned int*)mask;
    const unsigned short* ps = (const unsigned short*)mask;
    bool i32ok = true, f32ok = true, bfok = true;
    for (int i = tid; i < 4096; i += 256) {
        unsigned int v = pi[i];
        if (v > 1u) i32ok = false;
        if (v != 0u && v != 0x3F800000u) f32ok = false;
    }
    for (int i = tid; i < 4096; i += 256) {
        unsigned short v = ps[i];
        if (v != 0 && v != 0x3F80) bfok = false;
    }
    if (!i32ok) atomicAnd(&ok[0], 0);
    if (!f32ok) atomicAnd(&ok[1], 0);
    if (!bfok)  atomicAnd(&ok[2], 0);
    __syncthreads();
    if (tid == 0)
        g_maskmode = ok[0] ? 0 : (ok[1] ? 1 : (ok[2] ? 3 : 2));
}

__device__ __forceinline__ bool mask_at(const void* __restrict__ mask, size_t idx, int mode)
{
    if (mode == 0) return ((const int*)mask)[idx] != 0;
    if (mode == 1) return ((const float*)mask)[idx] != 0.0f;
    if (mode == 2) return ((const unsigned char*)mask)[idx] != 0;
    return ((const unsigned short*)mask)[idx] != 0;
}

// mask -> bitmap: one warp per 32-bit word, ballot
__global__ void __launch_bounds__(256) mask_to_bits(const void* __restrict__ mask)
{
    const int w = blockIdx.x * 8 + (threadIdx.x >> 5);
    const int lane = threadIdx.x & 31;
    const int mode = g_maskmode;
    size_t idx = (size_t)w * 32 + lane;
    bool m = mask_at(mask, idx, mode);
    uint32_t bits = __ballot_sync(0xffffffffu, m);
    if (lane == 0) g_maskbits[w] = bits;
}

// ======================= helpers =======================
__device__ __forceinline__ uint32_t smem_u32(const void* p) {
    uint32_t a;
    asm("{ .reg .u64 t; cvta.to.shared.u64 t, %1; cvt.u32.u64 %0, t; }" : "=r"(a) : "l"(p));
    return a;
}
__device__ __forceinline__ uint32_t swz64(uint32_t b)  { return b ^ ((b >> 3) & 0x30); }

// split f32 -> bf16 hi + bf16 lo
__device__ __forceinline__ void split4(float4 v, uint2& uh, uint2& ul)
{
    __nv_bfloat16 hx = __float2bfloat16(v.x), hy = __float2bfloat16(v.y);
    __nv_bfloat16 hz = __float2bfloat16(v.z), hw = __float2bfloat16(v.w);
    __nv_bfloat16 lx = __float2bfloat16(v.x - __bfloat162float(hx));
    __nv_bfloat16 ly = __float2bfloat16(v.y - __bfloat162float(hy));
    __nv_bfloat16 lz = __float2bfloat16(v.z - __bfloat162float(hz));
    __nv_bfloat16 lw = __float2bfloat16(v.w - __bfloat162float(hw));
    union { __nv_bfloat162 b2[2]; uint2 u; } th, tl;
    th.b2[0] = __halves2bfloat162(hx, hy); th.b2[1] = __halves2bfloat162(hz, hw);
    tl.b2[0] = __halves2bfloat162(lx, ly); tl.b2[1] = __halves2bfloat162(lz, lw);
    uh = th.u; ul = tl.u;
}

// streaming f32 -> split bf16 (hi/lo) converter; launch with grid*256 == n4
__global__ void __launch_bounds__(256) convert_split(const float4* __restrict__ src,
                                                     uint2* __restrict__ hi,
                                                     uint2* __restrict__ lo, int n4)
{
    int i = blockIdx.x * 256 + threadIdx.x;
    if (i < n4) {
        uint2 uh, ul; split4(src[i], uh, ul);
        hi[i] = uh; lo[i] = ul;
    }
}

#define CP16(saddr, gptr) \
    asm volatile("cp.async.cg.shared.global [%0], [%1], 16;" :: "r"(saddr), "l"(gptr))
#define CP_COMMIT() asm volatile("cp.async.commit_group;" ::: "memory")
#define CP_WAIT0()  asm volatile("cp.async.wait_group 0;" ::: "memory")

#define LDMX4(r, addr) \
    asm volatile("ldmatrix.sync.aligned.m8n8.x4.shared.b16 {%0,%1,%2,%3}, [%4];" \
        : "=r"((r)[0]), "=r"((r)[1]), "=r"((r)[2]), "=r"((r)[3]) : "r"(addr))

#define MMA_BF16(cc, a, b0_, b1_) \
    asm volatile("mma.sync.aligned.m16n8k16.row.col.f32.bf16.bf16.f32 " \
        "{%0,%1,%2,%3}, {%4,%5,%6,%7}, {%8,%9}, {%0,%1,%2,%3};" \
        : "+f"((cc)[0]), "+f"((cc)[1]), "+f"((cc)[2]), "+f"((cc)[3]) \
        : "r"((a)[0]), "r"((a)[1]), "r"((a)[2]), "r"((a)[3]), "r"(b0_), "r"(b1_))

// ======================= bf16x3 mma.sync GEMM, cp.async pipelined =======================
// MODE 0: dense  C = A * B^T (pre-split bf16). OUTBF: 1 -> split bf16 out, 0 -> f32 out
// MODE 1: qk     per bh: scores = mask ? -1e9 : (Q K^T)/8 -> f32 Cf  (bitmap mask)
// MODE 2: pv     per bh: ctx = attn(f32) @ V(split bf16) -> split bf16 ctx   (sync loads)
template<int MODE, int OUTBF>
__global__ void __launch_bounds__(256, 2) mma_gemm(
    const float* __restrict__ Af,
    const __nv_bfloat16* __restrict__ Ah_, const __nv_bfloat16* __restrict__ Al_,
    const __nv_bfloat16* __restrict__ Bh_, const __nv_bfloat16* __restrict__ Bl_,
    float* __restrict__ Cf,
    __nv_bfloat16* __restrict__ Ch_, __nv_bfloat16* __restrict__ Cl_)
{
    constexpr int BN    = (MODE == 2) ? 64 : 128;
    constexpr int NSTEP = (MODE == 0) ? 32 : ((MODE == 1) ? 2 : 64);
    constexpr int BNW   = BN / 2;
    constexpr int NF    = BNW / 8;
    // MODE 0/1 (pipelined): per-stage layout AH=0, AL=8192, BH=16384, BL=24576; stage stride 32768
    // MODE 2 (single buffer): AH=0, AL=8192, BH=16384, BL=20480
    constexpr int SM_AH = 0;
    constexpr int SM_AL = 8192;
    constexpr int SM_BH = 16384;
    constexpr int SM_BL = (MODE == 2) ? 20480 : 24576;

    extern __shared__ __align__(16) char smem[];

    const int tid = threadIdx.x, lane = tid & 31, wid = tid >> 5;
    const int bm = blockIdx.y * 128;
    const int bn = blockIdx.x * BN;

    int b = 0, h = 0;
    const __nv_bfloat16 *Ah = nullptr, *Al = nullptr, *Bh = nullptr, *Bl = nullptr;
    const float* Afp = nullptr;
    float* Cfp = nullptr;

    if (MODE == 0) {
        Ah = Ah_ + (size_t)bm * DM; Al = Al_ + (size_t)bm * DM;
        Bh = Bh_ + (size_t)bn * DM; Bl = Bl_ + (size_t)bn * DM;
        Cfp = Cf;
    } else if (MODE == 1) {
        int bh = blockIdx.z; b = bh >> 4; h = bh & 15;
        Ah = g_Qh + ((size_t)b * SQ + bm) * DM + h * DK;
        Al = g_Ql + ((size_t)b * SQ + bm) * DM + h * DK;
        Bh = g_Kh + ((size_t)b * SQ + bn) * DM + h * DK;
        Bl = g_Kl + ((size_t)b * SQ + bn) * DM + h * DK;
        Cfp = Cf + (size_t)bh * SQ * SQ;
    } else {
        int bh = blockIdx.z; b = bh >> 4; h = bh & 15;
        Afp = Af + (size_t)bh * SQ * SQ + (size_t)bm * SQ;
        Bh = g_Vh + (size_t)b * SQ * DM + h * DK;
        Bl = g_Vl + (size_t)b * SQ * DM + h * DK;
    }

    const uint32_t sb = smem_u32(smem);
    const int wm = (wid & 3) * 32;
    const int wn = (wid >> 2) * BNW;
    const int ar = lane & 15;
    const int ac = (lane >> 4) << 3;
    const int br = (lane & 7) + ((lane & 16) >> 1);
    const int bc = lane & 8;

    float c[2][NF][4];
    #pragma unroll
    for (int mi = 0; mi < 2; mi++)
        #pragma unroll
        for (int nf = 0; nf < NF; nf++)
            #pragma unroll
            for (int j = 0; j < 4; j++) c[mi][nf][j] = 0.f;

    if constexpr (MODE != 2) {
        // ---- cp.async 2-stage pipeline ----
        auto issue_stage = [&](int st, int k0) {
            const uint32_t sbase = sb + (uint32_t)st * 32768u;
            #pragma unroll
            for (int i = 0; i < 2; i++) {
                int idx = tid + (i << 8);
                int r = idx >> 2, c16 = (idx & 3) << 4;
                uint32_t sw = swz64((uint32_t)(r * 64 + c16));
                size_t go = ((size_t)r * DM + k0) * 2 + c16;
                CP16(sbase + SM_AH + sw, (const char*)Ah + go);
                CP16(sbase + SM_AL + sw, (const char*)Al + go);
                CP16(sbase + SM_BH + sw, (const char*)Bh + go);
                CP16(sbase + SM_BL + sw, (const char*)Bl + go);
            }
        };
        issue_stage(0, 0);
        CP_COMMIT();

        for (int it = 0; it < NSTEP; ++it) {
            CP_WAIT0();
            __syncthreads();      // stage (it&1) fully visible; all warps done with stage ((it+1)&1)
            if (it + 1 < NSTEP) { issue_stage((it + 1) & 1, (it + 1) * 32); CP_COMMIT(); }

            const uint32_t base = sb + (uint32_t)(it & 1) * 32768u;
            const uint32_t sAh = base + SM_AH, sAl = base + SM_AL;
            const uint32_t sBh = base + SM_BH, sBl = base + SM_BL;
            #pragma unroll
            for (int ks = 0; ks < 2; ++ks) {
                uint32_t ah[2][4], al[2][4];
                #pragma unroll
                for (int mi = 0; mi < 2; mi++) {
                    uint32_t off = swz64((uint32_t)((wm + mi * 16 + ar) * 64 + (ks * 16 + ac) * 2));
                    LDMX4(ah[mi], sAh + off);
                    LDMX4(al[mi], sAl + off);
                }
                #pragma unroll
                for (int p = 0; p < NF / 2; p++) {
                    uint32_t bh4[4], bl4[4];
                    uint32_t off = swz64((uint32_t)((wn + p * 16 + br) * 64 + (ks * 16 + bc) * 2));
                    LDMX4(bh4, sBh + off);
                    LDMX4(bl4, sBl + off);
                    #pragma unroll
                    for (int hh = 0; hh < 2; hh++)
                        #pragma unroll
                        for (int mi = 0; mi < 2; mi++)
                            MMA_BF16(c[mi][p * 2 + hh], ah[mi], bh4[hh * 2], bh4[hh * 2 + 1]);
                    #pragma unroll
                    for (int hh = 0; hh < 2; hh++)
                        #pragma unroll
                        for (int mi = 0; mi < 2; mi++)
                            MMA_BF16(c[mi][p * 2 + hh], ah[mi], bl4[hh * 2], bl4[hh * 2 + 1]);
                    #pragma unroll
                    for (int hh = 0; hh < 2; hh++)
                        #pragma unroll
                        for (int mi = 0; mi < 2; mi++)
                            MMA_BF16(c[mi][p * 2 + hh], al[mi], bh4[hh * 2], bh4[hh * 2 + 1]);
                }
            }
        }
    } else {
        // ---- MODE 2: synchronous single-buffer (attn read is DRAM-bound anyway) ----
        const uint32_t sAh = sb + SM_AH, sAl = sb + SM_AL;
        const uint32_t sBh = sb + SM_BH, sBl = sb + SM_BL;
        for (int it = 0; it < NSTEP; ++it) {
            const int k0 = it * 32;
            __syncthreads();
            {
                const float* src = Afp + k0;
                #pragma unroll
                for (int i = 0; i < 4; i++) {
                    int idx = tid + (i << 8);
                    int r = idx >> 3, c4 = (idx & 7) << 2;
                    float4 v = *(const float4*)(src + (size_t)r * SQ + c4);
                    uint2 uh, ul; split4(v, uh, ul);
                    uint32_t sw = swz64((uint32_t)(r * 64 + (c4 << 1)));
                    *(uint2*)(smem + SM_AH + sw) = uh;
                    *(uint2*)(smem + SM_AL + sw) = ul;
                }
            }
            {
                int kr = tid >> 3, n8 = (tid & 7) << 3;
                size_t go = ((size_t)(k0 + kr) * DM + n8) * 2;
                uint4 vh = *(const uint4*)((const char*)Bh + go);
                uint4 vl = *(const uint4*)((const char*)Bl + go);
                const __nv_bfloat16* ph = (const __nv_bfloat16*)&vh;
                const __nv_bfloat16* pl = (const __nv_bfloat16*)&vl;
                #pragma unroll
                for (int j = 0; j < 8; j++) {
                    uint32_t sw = swz64((uint32_t)((n8 + j) * 64 + kr * 2));
                    *(__nv_bfloat16*)(smem + SM_BH + sw) = ph[j];
                    *(__nv_bfloat16*)(smem + SM_BL + sw) = pl[j];
                }
            }
            __syncthreads();

            #pragma unroll
            for (int ks = 0; ks < 2; ++ks) {
                uint32_t ah[2][4], al[2][4];
                #pragma unroll
                for (int mi = 0; mi < 2; mi++) {
                    uint32_t off = swz64((uint32_t)((wm + mi * 16 + ar) * 64 + (ks * 16 + ac) * 2));
                    LDMX4(ah[mi], sAh + off);
                    LDMX4(al[mi], sAl + off);
                }
                #pragma unroll
                for (int p = 0; p < NF / 2; p++) {
                    uint32_t bh4[4], bl4[4];
                    uint32_t off = swz64((uint32_t)((wn + p * 16 + br) * 64 + (ks * 16 + bc) * 2));
                    LDMX4(bh4, sBh + off);
                    LDMX4(bl4, sBl + off);
                    #pragma unroll
                    for (int hh = 0; hh < 2; hh++)
                        #pragma unroll
                        for (int mi = 0; mi < 2; mi++)
                            MMA_BF16(c[mi][p * 2 + hh], ah[mi], bh4[hh * 2], bh4[hh * 2 + 1]);
                    #pragma unroll
                    for (int hh = 0; hh < 2; hh++)
                        #pragma unroll
                        for (int mi = 0; mi < 2; mi++)
                            MMA_BF16(c[mi][p * 2 + hh], ah[mi], bl4[hh * 2], bl4[hh * 2 + 1]);
                    #pragma unroll
                    for (int hh = 0; hh < 2; hh++)
                        #pragma unroll
                        for (int mi = 0; mi < 2; mi++)
                            MMA_BF16(c[mi][p * 2 + hh], al[mi], bh4[hh * 2], bh4[hh * 2 + 1]);
                }
            }
        }
    }

    // ---- epilogue ----
    #pragma unroll
    for (int mi = 0; mi < 2; mi++) {
        int row = bm + wm + mi * 16 + (lane >> 2);
        uint2 wa, wb;
        if (MODE == 1) {
            const uint32_t* mr = g_maskbits + ((size_t)b * SQ + row) * (SQ / 32) + ((bn + wn) >> 5);
            wa = *(const uint2*)mr;
            wb = *(const uint2*)(mr + 8 * (SQ / 32));
        }
        #pragma unroll
        for (int nf = 0; nf < NF; nf++) {
            int lc = nf * 8 + ((lane & 3) << 1);
            float2 v0 = make_float2(c[mi][nf][0], c[mi][nf][1]);
            float2 v1 = make_float2(c[mi][nf][2], c[mi][nf][3]);
            if (MODE == 1) {
                uint32_t w0 = (lc & 32) ? wa.y : wa.x;
                uint32_t w1 = (lc & 32) ? wb.y : wb.x;
                int sh = lc & 31;
                v0.x = (w0 >> sh) & 1       ? -1e9f : v0.x * 0.125f;
                v0.y = (w0 >> (sh + 1)) & 1 ? -1e9f : v0.y * 0.125f;
                v1.x = (w1 >> sh) & 1       ? -1e9f : v1.x * 0.125f;
                v1.y = (w1 >> (sh + 1)) & 1 ? -1e9f : v1.y * 0.125f;
                int col = bn + wn + lc;
                *(float2*)(Cfp + (size_t)row * SQ + col)       = v0;
                *(float2*)(Cfp + (size_t)(row + 8) * SQ + col) = v1;
            } else if (MODE == 0 && !OUTBF) {
                int col = bn + wn + lc;
                *(float2*)(Cfp + (size_t)row * DM + col)       = v0;
                *(float2*)(Cfp + (size_t)(row + 8) * DM + col) = v1;
            } else {
                size_t o0, o1;
                if (MODE == 0) {
                    int col = bn + wn + lc;
                    o0 = (size_t)row * DM + col;
                    o1 = (size_t)(row + 8) * DM + col;
                } else {
                    int col = wn + lc;
                    o0 = ((size_t)b * SQ + row) * DM + h * DK + col;
                    o1 = ((size_t)b * SQ + row + 8) * DM + h * DK + col;
                }
                __nv_bfloat16* Ch = (MODE == 0) ? Ch_ : g_ctxh;
                __nv_bfloat16* Cl = (MODE == 0) ? Cl_ : g_ctxl;
                __nv_bfloat16 h0 = __float2bfloat16(v0.x), h1 = __float2bfloat16(v0.y);
                __nv_bfloat16 h2 = __float2bfloat16(v1.x), h3 = __float2bfloat16(v1.y);
                *(__nv_bfloat162*)(Ch + o0) = __halves2bfloat162(h0, h1);
                *(__nv_bfloat162*)(Ch + o1) = __halves2bfloat162(h2, h3);
                *(__nv_bfloat162*)(Cl + o0) = __halves2bfloat162(
                    __float2bfloat16(v0.x - __bfloat162float(h0)),
                    __float2bfloat16(v0.y - __bfloat162float(h1)));
                *(__nv_bfloat162*)(Cl + o1) = __halves2bfloat162(
                    __float2bfloat16(v1.x - __bfloat162float(h2)),
                    __float2bfloat16(v1.y - __bfloat162float(h3)));
            }
        }
    }
}

// ---------------- row softmax over 2048, one block per row --------------------------
__global__ void __launch_bounds__(256) softmax_rows(const float* __restrict__ src,
                                                    float* __restrict__ dst)
{
    const size_t row = blockIdx.x;
    const float* x = src + row * SQ;
    float* y = dst + row * SQ;
    const int tid = threadIdx.x, lane = tid & 31, warp = tid >> 5;
    __shared__ float sm[8];
    float v[8];
    float m = -3.0e38f;
    #pragma unroll
    for (int i = 0; i < 8; i++) { v[i] = x[i * 256 + tid]; m = fmaxf(m, v[i]); }
    #pragma unroll
    for (int o = 16; o; o >>= 1) m = fmaxf(m, __shfl_xor_sync(0xffffffffu, m, o));
    if (lane == 0) sm[warp] = m;
    __syncthreads();
    m = sm[lane & 7];
    #pragma unroll
    for (int o = 4; o; o >>= 1) m = fmaxf(m, __shfl_xor_sync(0xffffffffu, m, o));
    float s = 0.f;
    #pragma unroll
    for (int i = 0; i < 8; i++) { v[i] = expf(v[i] - m); s += v[i]; }
    #pragma unroll
    for (int o = 16; o; o >>= 1) s += __shfl_xor_sync(0xffffffffu, s, o);
    __syncthreads();
    if (lane == 0) sm[warp] = s;
    __syncthreads();
    s = sm[lane & 7];
    #pragma unroll
    for (int o = 4; o; o >>= 1) s += __shfl_xor_sync(0xffffffffu, s, o);
    const float inv = 1.0f / s;
    #pragma unroll
    for (int i = 0; i < 8; i++) y[i * 256 + tid] = v[i] * inv;
}

// ---------------- out = LayerNorm(fc + residual), one block per row of 1024 ---------
__global__ void __launch_bounds__(256) add_ln(const float* __restrict__ res, float* __restrict__ dst)
{
    const size_t row = blockIdx.x;
    const float* f = g_fc + row * DM;
    const float* r = res + row * DM;
    float* o = dst + row * DM;
    const int tid = threadIdx.x, lane = tid & 31, warp = tid >> 5;
    __shared__ float sm[8];
    float x[4];
    float s = 0.f;
    #pragma unroll
    for (int i = 0; i < 4; i++) { x[i] = f[i * 256 + tid] + r[i * 256 + tid]; s += x[i]; }
    #pragma unroll
    for (int off = 16; off; off >>= 1) s += __shfl_xor_sync(0xffffffffu, s, off);
    if (lane == 0) sm[warp] = s;
    __syncthreads();
    s = sm[lane & 7];
    #pragma unroll
    for (int off = 4; off; off >>= 1) s += __shfl_xor_sync(0xffffffffu, s, off);
    const float mean = s * (1.0f / DM);
    float s2 = 0.f;
    #pragma unroll
    for (int i = 0; i < 4; i++) { float d = x[i] - mean; s2 += d * d; }
    #pragma unroll
    for (int off = 16; off; off >>= 1) s2 += __shfl_xor_sync(0xffffffffu, s2, off);
    __syncthreads();
    if (lane == 0) sm[warp] = s2;
    __syncthreads();
    s2 = sm[lane & 7];
    #pragma unroll
    for (int off = 4; off; off >>= 1) s2 += __shfl_xor_sync(0xffffffffu, s2, off);
    const float inv = rsqrtf(s2 * (1.0f / DM) + 1e-5f);
    #pragma unroll
    for (int i = 0; i < 4; i++) o[i * 256 + tid] = (x[i] - mean) * inv;
}

// ---------------- launch -----------------------------------------------------------
extern "C" void kernel_launch(void* const* d_in, const int* in_sizes, int n_in,
                              void* d_out, int out_size)
{
    const float* iQ  = (const float*)d_in[0];
    const float* iK  = (const float*)d_in[1];
    const float* iV  = (const float*)d_in[2];
    const void*  msk = d_in[3];
    const float* WQ  = (const float*)d_in[4];
    const float* WK  = (const float*)d_in[5];
    const float* WV  = (const float*)d_in[6];
    const float* Wfc = (const float*)d_in[7];
    float* out = (float*)d_out;

    const long long LN_N  = (long long)ROWS * DM;        // 4,194,304
    const long long ATT_N = (long long)BHN * SQ * SQ;    // 134,217,728
    float* attn_out = nullptr;
    float* ln_out   = out;
    if ((long long)out_size >= LN_N + ATT_N) {
        attn_out = out + LN_N;
    } else if ((long long)out_size == ATT_N) {
        attn_out = out;
        ln_out = nullptr;
    }

    void* p;
    cudaGetSymbolAddress(&p, g_attn); float* pAttn = (float*)p;
    cudaGetSymbolAddress(&p, g_fc);   float* pFc   = (float*)p;
    __nv_bfloat16 *inQh, *inQl, *inKh, *inKl, *inVh, *inVl;
    __nv_bfloat16 *wqh, *wql, *wkh, *wkl, *wvh, *wvl, *wfh, *wfl;
    __nv_bfloat16 *qh, *ql, *kh, *kl, *vh, *vl, *cth, *ctl;
    cudaGetSymbolAddress(&p, g_inQh); inQh = (__nv_bfloat16*)p;
    cudaGetSymbolAddress(&p, g_inQl); inQl = (__nv_bfloat16*)p;
    cudaGetSymbolAddress(&p, g_inKh); inKh = (__nv_bfloat16*)p;
    cudaGetSymbolAddress(&p, g_inKl); inKl = (__nv_bfloat16*)p;
    cudaGetSymbolAddress(&p, g_inVh); inVh = (__nv_bfloat16*)p;
    cudaGetSymbolAddress(&p, g_inVl); inVl = (__nv_bfloat16*)p;
    cudaGetSymbolAddress(&p, g_Wqh);  wqh = (__nv_bfloat16*)p;
    cudaGetSymbolAddress(&p, g_Wql);  wql = (__nv_bfloat16*)p;
    cudaGetSymbolAddress(&p, g_Wkh);  wkh = (__nv_bfloat16*)p;
    cudaGetSymbolAddress(&p, g_Wkl);  wkl = (__nv_bfloat16*)p;
    cudaGetSymbolAddress(&p, g_Wvh);  wvh = (__nv_bfloat16*)p;
    cudaGetSymbolAddress(&p, g_Wvl);  wvl = (__nv_bfloat16*)p;
    cudaGetSymbolAddress(&p, g_Wfh);  wfh = (__nv_bfloat16*)p;
    cudaGetSymbolAddress(&p, g_Wfl);  wfl = (__nv_bfloat16*)p;
    cudaGetSymbolAddress(&p, g_Qh);   qh  = (__nv_bfloat16*)p;
    cudaGetSymbolAddress(&p, g_Ql);   ql  = (__nv_bfloat16*)p;
    cudaGetSymbolAddress(&p, g_Kh);   kh  = (__nv_bfloat16*)p;
    cudaGetSymbolAddress(&p, g_Kl);   kl  = (__nv_bfloat16*)p;
    cudaGetSymbolAddress(&p, g_Vh);   vh  = (__nv_bfloat16*)p;
    cudaGetSymbolAddress(&p, g_Vl);   vl  = (__nv_bfloat16*)p;
    cudaGetSymbolAddress(&p, g_ctxh); cth = (__nv_bfloat16*)p;
    cudaGetSymbolAddress(&p, g_ctxl); ctl = (__nv_bfloat16*)p;

    static int attr_set = 0;
    if (!attr_set) {
        cudaFuncSetAttribute(mma_gemm<0,1>, cudaFuncAttributeMaxDynamicSharedMemorySize, 65536);
        cudaFuncSetAttribute(mma_gemm<0,0>, cudaFuncAttributeMaxDynamicSharedMemorySize, 65536);
        cudaFuncSetAttribute(mma_gemm<1,0>, cudaFuncAttributeMaxDynamicSharedMemorySize, 65536);
        attr_set = 1;
    }

    detect_mask_kernel<<<1, 256>>>(msk);
    mask_to_bits<<<(BB * SQ * SQ / 32) / 8, 256>>>(msk);

    // pre-split inputs and weights to bf16 hi/lo (exact-size grids, 1 chunk/thread)
    const int NIN4 = ROWS * DM / 4, NW4 = DM * DM / 4;
    convert_split<<<NIN4 / 256, 256>>>((const float4*)iQ,  (uint2*)inQh, (uint2*)inQl, NIN4);
    convert_split<<<NIN4 / 256, 256>>>((const float4*)iK,  (uint2*)inKh, (uint2*)inKl, NIN4);
    convert_split<<<NIN4 / 256, 256>>>((const float4*)iV,  (uint2*)inVh, (uint2*)inVl, NIN4);
    convert_split<<<NW4 / 256,  256>>>((const float4*)WQ,  (uint2*)wqh,  (uint2*)wql,  NW4);
    convert_split<<<NW4 / 256,  256>>>((const float4*)WK,  (uint2*)wkh,  (uint2*)wkl,  NW4);
    convert_split<<<NW4 / 256,  256>>>((const float4*)WV,  (uint2*)wvh,  (uint2*)wvl,  NW4);
    convert_split<<<NW4 / 256,  256>>>((const float4*)Wfc, (uint2*)wfh,  (uint2*)wfl,  NW4);

    // projections: split bf16 in, split-bf16 out
    dim3 gp(DM / 128, ROWS / 128);               // (8, 32)
    mma_gemm<0,1><<<gp, 256, 65536>>>(nullptr, inQh, inQl, wqh, wql, nullptr, qh, ql);
    mma_gemm<0,1><<<gp, 256, 65536>>>(nullptr, inKh, inKl, wkh, wkl, nullptr, kh, kl);
    mma_gemm<0,1><<<gp, 256, 65536>>>(nullptr, inVh, inVl, wvh, wvl, nullptr, vh, vl);

    // qk scores -> g_attn scratch
    dim3 gs(SQ / 128, SQ / 128, BHN);            // (16, 16, 32)
    mma_gemm<1,0><<<gs, 256, 65536>>>(nullptr, nullptr, nullptr, nullptr, nullptr, pAttn, nullptr, nullptr);

    float* attn_dst = attn_out ? attn_out : pAttn;
    softmax_rows<<<(unsigned)(BHN * SQ), 256>>>(pAttn, attn_dst);

    // pv: attn f32 + V split bf16 -> ctx split bf16
    dim3 gv(1, SQ / 128, BHN);                   // (1, 16, 32)
    mma_gemm<2,1><<<gv, 256, 24576>>>(attn_dst, nullptr, nullptr, nullptr, nullptr, nullptr, nullptr, nullptr);

    // fc: ctx bf16 @ Wfc bf16 -> f32
    mma_gemm<0,0><<<gp, 256, 65536>>>(nullptr, cth, ctl, wfh, wfl, pFc, nullptr, nullptr);

    add_ln<<<(unsigned)ROWS, 256>>>(iQ, ln_out);
}

// round 17
// speedup vs baseline: 1.2677x; 1.0142x over previous
#include <cuda_runtime.h>
#include <cuda_bf16.h>
#include <math.h>
#include <stdint.h>

// Problem dims
#define SQ   2048
#define DM   1024
#define NH   16
#define DK   64
#define BB   2
#define ROWS (BB*SQ)   // 4096
#define BHN  (BB*NH)   // 32

// ---------------- scratch (static device memory; no allocs allowed) ----------------
__device__ __nv_bfloat16 g_inQh[(size_t)ROWS*DM], g_inQl[(size_t)ROWS*DM];
__device__ __nv_bfloat16 g_inKh[(size_t)ROWS*DM], g_inKl[(size_t)ROWS*DM];
__device__ __nv_bfloat16 g_inVh[(size_t)ROWS*DM], g_inVl[(size_t)ROWS*DM];
__device__ __nv_bfloat16 g_Wqh[(size_t)DM*DM], g_Wql[(size_t)DM*DM];
__device__ __nv_bfloat16 g_Wkh[(size_t)DM*DM], g_Wkl[(size_t)DM*DM];
__device__ __nv_bfloat16 g_Wvh[(size_t)DM*DM], g_Wvl[(size_t)DM*DM];
__device__ __nv_bfloat16 g_Wfh[(size_t)DM*DM], g_Wfl[(size_t)DM*DM];
__device__ __nv_bfloat16 g_Qh[(size_t)ROWS*DM], g_Ql[(size_t)ROWS*DM];
__device__ __nv_bfloat16 g_Kh[(size_t)ROWS*DM], g_Kl[(size_t)ROWS*DM];
__device__ __nv_bfloat16 g_Vh[(size_t)ROWS*DM], g_Vl[(size_t)ROWS*DM];
__device__ __nv_bfloat16 g_ctxh[(size_t)ROWS*DM], g_ctxl[(size_t)ROWS*DM];
__device__ float g_fc [ (size_t)ROWS*DM ];
__device__ float g_attn[ (size_t)BHN*SQ*SQ ];            // attn dump when not in d_out
__device__ uint32_t g_maskbits[ (size_t)BB*SQ*SQ/32 ];   // 1 bit per (b,q,k)
__device__ int   g_maskmode;

// ---------------- mask dtype detection ----------------
__global__ void detect_mask_kernel(const void* __restrict__ mask)
{
    __shared__ int ok[3];
    int tid = threadIdx.x;
    if (tid < 3) ok[tid] = 1;
    __syncthreads();
    const unsigned int*   pi = (const unsigned int*)mask;
    const unsigned short* ps = (const unsigned short*)mask;
    bool i32ok = true, f32ok = true, bfok = true;
    for (int i = tid; i < 4096; i += 256) {
        unsigned int v = pi[i];
        if (v > 1u) i32ok = false;
        if (v != 0u && v != 0x3F800000u) f32ok = false;
    }
    for (int i = tid; i < 4096; i += 256) {
        unsigned short v = ps[i];
        if (v != 0 && v != 0x3F80) bfok = false;
    }
    if (!i32ok) atomicAnd(&ok[0], 0);
    if (!f32ok) atomicAnd(&ok[1], 0);
    if (!bfok)  atomicAnd(&ok[2], 0);
    __syncthreads();
    if (tid == 0)
        g_maskmode = ok[0] ? 0 : (ok[1] ? 1 : (ok[2] ? 3 : 2));
}

__device__ __forceinline__ bool mask_at(const void* __restrict__ mask, size_t idx, int mode)
{
    if (mode == 0) return ((const int*)mask)[idx] != 0;
    if (mode == 1) return ((const float*)mask)[idx] != 0.0f;
    if (mode == 2) return ((const unsigned char*)mask)[idx] != 0;
    return ((const unsigned short*)mask)[idx] != 0;
}

// mask -> bitmap: one warp per 32-bit word, ballot
__global__ void __launch_bounds__(256) mask_to_bits(const void* __restrict__ mask)
{
    const int w = blockIdx.x * 8 + (threadIdx.x >> 5);
    const int lane = threadIdx.x & 31;
    const int mode = g_maskmode;
    size_t idx = (size_t)w * 32 + lane;
    bool m = mask_at(mask, idx, mode);
    uint32_t bits = __ballot_sync(0xffffffffu, m);
    if (lane == 0) g_maskbits[w] = bits;
}

// ======================= helpers =======================
__device__ __forceinline__ uint32_t smem_u32(const void* p) {
    uint32_t a;
    asm("{ .reg .u64 t; cvta.to.shared.u64 t, %1; cvt.u32.u64 %0, t; }" : "=r"(a) : "l"(p));
    return a;
}
__device__ __forceinline__ uint32_t swz64(uint32_t b)  { return b ^ ((b >> 3) & 0x30); }

// split f32 -> bf16 hi + bf16 lo
__device__ __forceinline__ void split4(float4 v, uint2& uh, uint2& ul)
{
    __nv_bfloat16 hx = __float2bfloat16(v.x), hy = __float2bfloat16(v.y);
    __nv_bfloat16 hz = __float2bfloat16(v.z), hw = __float2bfloat16(v.w);
    __nv_bfloat16 lx = __float2bfloat16(v.x - __bfloat162float(hx));
    __nv_bfloat16 ly = __float2bfloat16(v.y - __bfloat162float(hy));
    __nv_bfloat16 lz = __float2bfloat16(v.z - __bfloat162float(hz));
    __nv_bfloat16 lw = __float2bfloat16(v.w - __bfloat162float(hw));
    union { __nv_bfloat162 b2[2]; uint2 u; } th, tl;
    th.b2[0] = __halves2bfloat162(hx, hy); th.b2[1] = __halves2bfloat162(hz, hw);
    tl.b2[0] = __halves2bfloat162(lx, ly); tl.b2[1] = __halves2bfloat162(lz, lw);
    uh = th.u; ul = tl.u;
}

// one launch converting all 7 tensors; grid (4096, 7)
struct ConvArgs {
    const float4* src[7];
    uint2* hi[7];
    uint2* lo[7];
    int n4[7];
};
__global__ void __launch_bounds__(256) convert_all(ConvArgs a)
{
    const int t = blockIdx.y;
    int i = blockIdx.x * 256 + threadIdx.x;
    if (i < a.n4[t]) {
        uint2 uh, ul; split4(a.src[t][i], uh, ul);
        a.hi[t][i] = uh; a.lo[t][i] = ul;
    }
}

#define CP16(saddr, gptr) \
    asm volatile("cp.async.cg.shared.global [%0], [%1], 16;" :: "r"(saddr), "l"(gptr))
#define CP_COMMIT() asm volatile("cp.async.commit_group;" ::: "memory")
#define CP_WAIT0()  asm volatile("cp.async.wait_group 0;" ::: "memory")

#define LDMX4(r, addr) \
    asm volatile("ldmatrix.sync.aligned.m8n8.x4.shared.b16 {%0,%1,%2,%3}, [%4];" \
        : "=r"((r)[0]), "=r"((r)[1]), "=r"((r)[2]), "=r"((r)[3]) : "r"(addr))

#define MMA_BF16(cc, a, b0_, b1_) \
    asm volatile("mma.sync.aligned.m16n8k16.row.col.f32.bf16.bf16.f32 " \
        "{%0,%1,%2,%3}, {%4,%5,%6,%7}, {%8,%9}, {%0,%1,%2,%3};" \
        : "+f"((cc)[0]), "+f"((cc)[1]), "+f"((cc)[2]), "+f"((cc)[3]) \
        : "r"((a)[0]), "r"((a)[1]), "r"((a)[2]), "r"((a)[3]), "r"(b0_), "r"(b1_))

// ======================= bf16x3 mma.sync GEMM, cp.async pipelined =======================
// MODE 0: dense  C = A * B^T (pre-split bf16). OUTBF: 1 -> split bf16 out, 0 -> f32 out
// MODE 1: qk     per bh: scores = mask ? -1e9 : (Q K^T)/8 -> f32 Cf  (bitmap mask)
// MODE 2: pv     per bh: ctx = attn(f32) @ V(split bf16) -> split bf16 ctx (cp.async raw staging)
// MODE 3: QKV    packed projections; blockIdx.z selects {Q,K,V} tensors from device symbols
template<int MODE, int OUTBF>
__global__ void __launch_bounds__(256, 2) mma_gemm(
    const float* __restrict__ Af,
    const __nv_bfloat16* __restrict__ Ah_, const __nv_bfloat16* __restrict__ Al_,
    const __nv_bfloat16* __restrict__ Bh_, const __nv_bfloat16* __restrict__ Bl_,
    float* __restrict__ Cf,
    __nv_bfloat16* __restrict__ Ch_, __nv_bfloat16* __restrict__ Cl_)
{
    constexpr int BN    = (MODE == 2) ? 64 : 128;
    constexpr int NSTEP = (MODE == 1) ? 2 : ((MODE == 2) ? 64 : 32);
    constexpr int BNW   = BN / 2;
    constexpr int NF    = BNW / 8;
    // MODE 0/1/3 (pipelined): per-stage AH=0, AL=8192, BH=16384, BL=24576; stage stride 32768
    constexpr int SM_AH = 0;
    constexpr int SM_AL = 8192;
    constexpr int SM_BH = 16384;
    constexpr int SM_BL = 24576;
    // MODE 2: raw staging + single operand buffer
    constexpr int RAW_A  = 0;       // 2 x 16384 f32 tile
    constexpr int RAW_VH = 32768;   // 2 x 4096
    constexpr int RAW_VL = 40960;   // 2 x 4096
    constexpr int OP_AH  = 49152;
    constexpr int OP_AL  = 57344;
    constexpr int OP_BH  = 65536;
    constexpr int OP_BL  = 69632;   // total 73728

    extern __shared__ __align__(16) char smem[];

    const int tid = threadIdx.x, lane = tid & 31, wid = tid >> 5;
    const int bm = blockIdx.y * 128;
    const int bn = blockIdx.x * BN;

    int b = 0, h = 0;
    const __nv_bfloat16 *Ah = nullptr, *Al = nullptr, *Bh = nullptr, *Bl = nullptr;
    const float* Afp = nullptr;
    float* Cfp = nullptr;
    __nv_bfloat16 *Chp = nullptr, *Clp = nullptr;

    if (MODE == 0) {
        Ah = Ah_ + (size_t)bm * DM; Al = Al_ + (size_t)bm * DM;
        Bh = Bh_ + (size_t)bn * DM; Bl = Bl_ + (size_t)bn * DM;
        Cfp = Cf; Chp = Ch_; Clp = Cl_;
    } else if (MODE == 3) {
        int z = blockIdx.z;
        Ah = (z == 0 ? g_inQh : z == 1 ? g_inKh : g_inVh) + (size_t)bm * DM;
        Al = (z == 0 ? g_inQl : z == 1 ? g_inKl : g_inVl) + (size_t)bm * DM;
        Bh = (z == 0 ? g_Wqh  : z == 1 ? g_Wkh  : g_Wvh)  + (size_t)bn * DM;
        Bl = (z == 0 ? g_Wql  : z == 1 ? g_Wkl  : g_Wvl)  + (size_t)bn * DM;
        Chp = (z == 0 ? g_Qh : z == 1 ? g_Kh : g_Vh);
        Clp = (z == 0 ? g_Ql : z == 1 ? g_Kl : g_Vl);
    } else if (MODE == 1) {
        int bh = blockIdx.z; b = bh >> 4; h = bh & 15;
        Ah = g_Qh + ((size_t)b * SQ + bm) * DM + h * DK;
        Al = g_Ql + ((size_t)b * SQ + bm) * DM + h * DK;
        Bh = g_Kh + ((size_t)b * SQ + bn) * DM + h * DK;
        Bl = g_Kl + ((size_t)b * SQ + bn) * DM + h * DK;
        Cfp = Cf + (size_t)bh * SQ * SQ;
    } else {
        int bh = blockIdx.z; b = bh >> 4; h = bh & 15;
        Afp = Af + (size_t)bh * SQ * SQ + (size_t)bm * SQ;
        Bh = g_Vh + (size_t)b * SQ * DM + h * DK;
        Bl = g_Vl + (size_t)b * SQ * DM + h * DK;
    }

    const uint32_t sb = smem_u32(smem);
    const int wm = (wid & 3) * 32;
    const int wn = (wid >> 2) * BNW;
    const int ar = lane & 15;
    const int ac = (lane >> 4) << 3;
    const int br = (lane & 7) + ((lane & 16) >> 1);
    const int bc = lane & 8;

    float c[2][NF][4];
    #pragma unroll
    for (int mi = 0; mi < 2; mi++)
        #pragma unroll
        for (int nf = 0; nf < NF; nf++)
            #pragma unroll
            for (int j = 0; j < 4; j++) c[mi][nf][j] = 0.f;

    if constexpr (MODE != 2) {
        // ---- cp.async 2-stage pipeline (pure split-bf16 copies) ----
        auto issue_stage = [&](int st, int k0) {
            const uint32_t sbase = sb + (uint32_t)st * 32768u;
            #pragma unroll
            for (int i = 0; i < 2; i++) {
                int idx = tid + (i << 8);
                int r = idx >> 2, c16 = (idx & 3) << 4;
                uint32_t sw = swz64((uint32_t)(r * 64 + c16));
                size_t go = ((size_t)r * DM + k0) * 2 + c16;
                CP16(sbase + SM_AH + sw, (const char*)Ah + go);
                CP16(sbase + SM_AL + sw, (const char*)Al + go);
                CP16(sbase + SM_BH + sw, (const char*)Bh + go);
                CP16(sbase + SM_BL + sw, (const char*)Bl + go);
            }
        };
        issue_stage(0, 0);
        CP_COMMIT();

        for (int it = 0; it < NSTEP; ++it) {
            CP_WAIT0();
            __syncthreads();
            if (it + 1 < NSTEP) { issue_stage((it + 1) & 1, (it + 1) * 32); CP_COMMIT(); }

            const uint32_t base = sb + (uint32_t)(it & 1) * 32768u;
            const uint32_t sAh = base + SM_AH, sAl = base + SM_AL;
            const uint32_t sBh = base + SM_BH, sBl = base + SM_BL;
            #pragma unroll
            for (int ks = 0; ks < 2; ++ks) {
                uint32_t ah[2][4], al[2][4];
                #pragma unroll
                for (int mi = 0; mi < 2; mi++) {
                    uint32_t off = swz64((uint32_t)((wm + mi * 16 + ar) * 64 + (ks * 16 + ac) * 2));
                    LDMX4(ah[mi], sAh + off);
                    LDMX4(al[mi], sAl + off);
                }
                #pragma unroll
                for (int p = 0; p < NF / 2; p++) {
                    uint32_t bh4[4], bl4[4];
                    uint32_t off = swz64((uint32_t)((wn + p * 16 + br) * 64 + (ks * 16 + bc) * 2));
                    LDMX4(bh4, sBh + off);
                    LDMX4(bl4, sBl + off);
                    #pragma unroll
                    for (int hh = 0; hh < 2; hh++)
                        #pragma unroll
                        for (int mi = 0; mi < 2; mi++)
                            MMA_BF16(c[mi][p * 2 + hh], ah[mi], bh4[hh * 2], bh4[hh * 2 + 1]);
                    #pragma unroll
                    for (int hh = 0; hh < 2; hh++)
                        #pragma unroll
                        for (int mi = 0; mi < 2; mi++)
                            MMA_BF16(c[mi][p * 2 + hh], ah[mi], bl4[hh * 2], bl4[hh * 2 + 1]);
                    #pragma unroll
                    for (int hh = 0; hh < 2; hh++)
                        #pragma unroll
                        for (int mi = 0; mi < 2; mi++)
                            MMA_BF16(c[mi][p * 2 + hh], al[mi], bh4[hh * 2], bh4[hh * 2 + 1]);
                }
            }
        }
    } else {
        // ---- MODE 2: cp.async raw staging (f32 attn + split V), smem-side conversion ----
        auto issue_stage2 = [&](int st, int k0) {
            const uint32_t aBase = sb + RAW_A  + (uint32_t)st * 16384u;
            const uint32_t hBase = sb + RAW_VH + (uint32_t)st * 4096u;
            const uint32_t lBase = sb + RAW_VL + (uint32_t)st * 4096u;
            // A: 128 rows x 32 f32 = 1024 x 16B, 4/thread
            #pragma unroll
            for (int i = 0; i < 4; i++) {
                int cidx = tid + (i << 8);
                int r = cidx >> 3, off = (cidx & 7) << 4;
                size_t go = ((size_t)r * SQ + k0) * 4 + off;
                CP16(aBase + (uint32_t)(r * 128 + off), (const char*)Afp + go);
            }
            // V: 32 k-rows x 64 bf16 = 256 x 16B per array, 1/thread each
            {
                int r = tid >> 3, off = (tid & 7) << 4;
                size_t go = ((size_t)(k0 + r) * DM) * 2 + off;
                uint32_t so = (uint32_t)(r * 128 + off);
                CP16(hBase + so, (const char*)Bh + go);
                CP16(lBase + so, (const char*)Bl + go);
            }
        };
        issue_stage2(0, 0);
        CP_COMMIT();

        for (int it = 0; it < NSTEP; ++it) {
            CP_WAIT0();
            __syncthreads();           // raw stage ready AND operand buffers free
            if (it + 1 < NSTEP) { issue_stage2((it + 1) & 1, (it + 1) * 32); CP_COMMIT(); }

            const int st = it & 1;
            // convert A: smem f32 -> split bf16 operands (sequential 16B reads, conflict-free)
            {
                const char* rawA = smem + RAW_A + st * 16384;
                #pragma unroll
                for (int i = 0; i < 4; i++) {
                    int cidx = tid + (i << 8);
                    int r = cidx >> 3, c4 = (cidx & 7) << 2;
                    float4 v = *(const float4*)(rawA + r * 128 + c4 * 4);
                    uint2 uh, ul; split4(v, uh, ul);
                    uint32_t sw = swz64((uint32_t)(r * 64 + (c4 << 1)));
                    *(uint2*)(smem + OP_AH + sw) = uh;
                    *(uint2*)(smem + OP_AL + sw) = ul;
                }
            }
            // transpose-copy V from raw smem
            {
                const char* rawH = smem + RAW_VH + st * 4096;
                const char* rawL = smem + RAW_VL + st * 4096;
                int kr = tid >> 3, n8 = (tid & 7) << 3;
                uint4 vh = *(const uint4*)(rawH + kr * 128 + n8 * 2);
                uint4 vl = *(const uint4*)(rawL + kr * 128 + n8 * 2);
                const __nv_bfloat16* ph = (const __nv_bfloat16*)&vh;
                const __nv_bfloat16* pl = (const __nv_bfloat16*)&vl;
                #pragma unroll
                for (int j = 0; j < 8; j++) {
                    uint32_t sw = swz64((uint32_t)((n8 + j) * 64 + kr * 2));
                    *(__nv_bfloat16*)(smem + OP_BH + sw) = ph[j];
                    *(__nv_bfloat16*)(smem + OP_BL + sw) = pl[j];
                }
            }
            __syncthreads();

            const uint32_t sAh = sb + OP_AH, sAl = sb + OP_AL;
            const uint32_t sBh = sb + OP_BH, sBl = sb + OP_BL;
            #pragma unroll
            for (int ks = 0; ks < 2; ++ks) {
                uint32_t ah[2][4], al[2][4];
                #pragma unroll
                for (int mi = 0; mi < 2; mi++) {
                    uint32_t off = swz64((uint32_t)((wm + mi * 16 + ar) * 64 + (ks * 16 + ac) * 2));
                    LDMX4(ah[mi], sAh + off);
                    LDMX4(al[mi], sAl + off);
                }
                #pragma unroll
                for (int p = 0; p < NF / 2; p++) {
                    uint32_t bh4[4], bl4[4];
                    uint32_t off = swz64((uint32_t)((wn + p * 16 + br) * 64 + (ks * 16 + bc) * 2));
                    LDMX4(bh4, sBh + off);
                    LDMX4(bl4, sBl + off);
                    #pragma unroll
                    for (int hh = 0; hh < 2; hh++)
                        #pragma unroll
                        for (int mi = 0; mi < 2; mi++)
                            MMA_BF16(c[mi][p * 2 + hh], ah[mi], bh4[hh * 2], bh4[hh * 2 + 1]);
                    #pragma unroll
                    for (int hh = 0; hh < 2; hh++)
                        #pragma unroll
                        for (int mi = 0; mi < 2; mi++)
                            MMA_BF16(c[mi][p * 2 + hh], ah[mi], bl4[hh * 2], bl4[hh * 2 + 1]);
                    #pragma unroll
                    for (int hh = 0; hh < 2; hh++)
                        #pragma unroll
                        for (int mi = 0; mi < 2; mi++)
                            MMA_BF16(c[mi][p * 2 + hh], al[mi], bh4[hh * 2], bh4[hh * 2 + 1]);
                }
            }
        }
    }

    // ---- epilogue ----
    #pragma unroll
    for (int mi = 0; mi < 2; mi++) {
        int row = bm + wm + mi * 16 + (lane >> 2);
        uint2 wa, wb;
        if (MODE == 1) {
            const uint32_t* mr = g_maskbits + ((size_t)b * SQ + row) * (SQ / 32) + ((bn + wn) >> 5);
            wa = *(const uint2*)mr;
            wb = *(const uint2*)(mr + 8 * (SQ / 32));
        }
        #pragma unroll
        for (int nf = 0; nf < NF; nf++) {
            int lc = nf * 8 + ((lane & 3) << 1);
            float2 v0 = make_float2(c[mi][nf][0], c[mi][nf][1]);
            float2 v1 = make_float2(c[mi][nf][2], c[mi][nf][3]);
            if (MODE == 1) {
                uint32_t w0 = (lc & 32) ? wa.y : wa.x;
                uint32_t w1 = (lc & 32) ? wb.y : wb.x;
                int sh = lc & 31;
                v0.x = (w0 >> sh) & 1       ? -1e9f : v0.x * 0.125f;
                v0.y = (w0 >> (sh + 1)) & 1 ? -1e9f : v0.y * 0.125f;
                v1.x = (w1 >> sh) & 1       ? -1e9f : v1.x * 0.125f;
                v1.y = (w1 >> (sh + 1)) & 1 ? -1e9f : v1.y * 0.125f;
                int col = bn + wn + lc;
                *(float2*)(Cfp + (size_t)row * SQ + col)       = v0;
                *(float2*)(Cfp + (size_t)(row + 8) * SQ + col) = v1;
            } else if (MODE == 0 && !OUTBF) {
                int col = bn + wn + lc;
                *(float2*)(Cfp + (size_t)row * DM + col)       = v0;
                *(float2*)(Cfp + (size_t)(row + 8) * DM + col) = v1;
            } else {
                size_t o0, o1;
                __nv_bfloat16 *Ch, *Cl;
                if (MODE == 0 || MODE == 3) {
                    int col = bn + wn + lc;
                    o0 = (size_t)row * DM + col;
                    o1 = (size_t)(row + 8) * DM + col;
                    Ch = Chp; Cl = Clp;
                } else {
                    int col = wn + lc;
                    o0 = ((size_t)b * SQ + row) * DM + h * DK + col;
                    o1 = ((size_t)b * SQ + row + 8) * DM + h * DK + col;
                    Ch = g_ctxh; Cl = g_ctxl;
                }
                __nv_bfloat16 h0 = __float2bfloat16(v0.x), h1 = __float2bfloat16(v0.y);
                __nv_bfloat16 h2 = __float2bfloat16(v1.x), h3 = __float2bfloat16(v1.y);
                *(__nv_bfloat162*)(Ch + o0) = __halves2bfloat162(h0, h1);
                *(__nv_bfloat162*)(Ch + o1) = __halves2bfloat162(h2, h3);
                *(__nv_bfloat162*)(Cl + o0) = __halves2bfloat162(
                    __float2bfloat16(v0.x - __bfloat162float(h0)),
                    __float2bfloat16(v0.y - __bfloat162float(h1)));
                *(__nv_bfloat162*)(Cl + o1) = __halves2bfloat162(
                    __float2bfloat16(v1.x - __bfloat162float(h2)),
                    __float2bfloat16(v1.y - __bfloat162float(h3)));
            }
        }
    }
}

// ---------------- row softmax over 2048, one block per row, float4 ------------------
__global__ void __launch_bounds__(256) softmax_rows(const float* __restrict__ src,
                                                    float* __restrict__ dst)
{
    const size_t row = blockIdx.x;
    const float4* x4 = (const float4*)(src + row * SQ);
    float4* y4 = (float4*)(dst + row * SQ);
    const int tid = threadIdx.x, lane = tid & 31, warp = tid >> 5;
    __shared__ float sm[8];
    float4 va = x4[tid], vb = x4[tid + 256];
    float m = fmaxf(fmaxf(fmaxf(va.x, va.y), fmaxf(va.z, va.w)),
                    fmaxf(fmaxf(vb.x, vb.y), fmaxf(vb.z, vb.w)));
    #pragma unroll
    for (int o = 16; o; o >>= 1) m = fmaxf(m, __shfl_xor_sync(0xffffffffu, m, o));
    if (lane == 0) sm[warp] = m;
    __syncthreads();
    m = sm[lane & 7];
    #pragma unroll
    for (int o = 4; o; o >>= 1) m = fmaxf(m, __shfl_xor_sync(0xffffffffu, m, o));
    va.x = expf(va.x - m); va.y = expf(va.y - m); va.z = expf(va.z - m); va.w = expf(va.w - m);
    vb.x = expf(vb.x - m); vb.y = expf(vb.y - m); vb.z = expf(vb.z - m); vb.w = expf(vb.w - m);
    float s = va.x + va.y + va.z + va.w + vb.x + vb.y + vb.z + vb.w;
    #pragma unroll
    for (int o = 16; o; o >>= 1) s += __shfl_xor_sync(0xffffffffu, s, o);
    __syncthreads();
    if (lane == 0) sm[warp] = s;
    __syncthreads();
    s = sm[lane & 7];
    #pragma unroll
    for (int o = 4; o; o >>= 1) s += __shfl_xor_sync(0xffffffffu, s, o);
    const float inv = 1.0f / s;
    va.x *= inv; va.y *= inv; va.z *= inv; va.w *= inv;
    vb.x *= inv; vb.y *= inv; vb.z *= inv; vb.w *= inv;
    y4[tid] = va; y4[tid + 256] = vb;
}

// ---------------- out = LayerNorm(fc + residual), one block per row of 1024 ---------
__global__ void __launch_bounds__(256) add_ln(const float* __restrict__ res, float* __restrict__ dst)
{
    const size_t row = blockIdx.x;
    const float* f = g_fc + row * DM;
    const float* r = res + row * DM;
    float* o = dst + row * DM;
    const int tid = threadIdx.x, lane = tid & 31, warp = tid >> 5;
    __shared__ float sm[8];
    float x[4];
    float s = 0.f;
    #pragma unroll
    for (int i = 0; i < 4; i++) { x[i] = f[i * 256 + tid] + r[i * 256 + tid]; s += x[i]; }
    #pragma unroll
    for (int off = 16; off; off >>= 1) s += __shfl_xor_sync(0xffffffffu, s, off);
    if (lane == 0) sm[warp] = s;
    __syncthreads();
    s = sm[lane & 7];
    #pragma unroll
    for (int off = 4; off; off >>= 1) s += __shfl_xor_sync(0xffffffffu, s, off);
    const float mean = s * (1.0f / DM);
    float s2 = 0.f;
    #pragma unroll
    for (int i = 0; i < 4; i++) { float d = x[i] - mean; s2 += d * d; }
    #pragma unroll
    for (int off = 16; off; off >>= 1) s2 += __shfl_xor_sync(0xffffffffu, s2, off);
    __syncthreads();
    if (lane == 0) sm[warp] = s2;
    __syncthreads();
    s2 = sm[lane & 7];
    #pragma unroll
    for (int off = 4; off; off >>= 1) s2 += __shfl_xor_sync(0xffffffffu, s2, off);
    const float inv = rsqrtf(s2 * (1.0f / DM) + 1e-5f);
    #pragma unroll
    for (int i = 0; i < 4; i++) o[i * 256 + tid] = (x[i] - mean) * inv;
}

// ---------------- launch -----------------------------------------------------------
extern "C" void kernel_launch(void* const* d_in, const int* in_sizes, int n_in,
                              void* d_out, int out_size)
{
    const float* iQ  = (const float*)d_in[0];
    const float* iK  = (const float*)d_in[1];
    const float* iV  = (const float*)d_in[2];
    const void*  msk = d_in[3];
    const float* WQ  = (const float*)d_in[4];
    const float* WK  = (const float*)d_in[5];
    const float* WV  = (const float*)d_in[6];
    const float* Wfc = (const float*)d_in[7];
    float* out = (float*)d_out;

    const long long LN_N  = (long long)ROWS * DM;        // 4,194,304
    const long long ATT_N = (long long)BHN * SQ * SQ;    // 134,217,728
    float* attn_out = nullptr;
    float* ln_out   = out;
    if ((long long)out_size >= LN_N + ATT_N) {
        attn_out = out + LN_N;
    } else if ((long long)out_size == ATT_N) {
        attn_out = out;
        ln_out = nullptr;
    }

    void* p;
    cudaGetSymbolAddress(&p, g_attn); float* pAttn = (float*)p;
    cudaGetSymbolAddress(&p, g_fc);   float* pFc   = (float*)p;
    __nv_bfloat16 *inQh, *inQl, *inKh, *inKl, *inVh, *inVl;
    __nv_bfloat16 *wqh, *wql, *wkh, *wkl, *wvh, *wvl, *wfh, *wfl;
    __nv_bfloat16 *cth, *ctl;
    cudaGetSymbolAddress(&p, g_inQh); inQh = (__nv_bfloat16*)p;
    cudaGetSymbolAddress(&p, g_inQl); inQl = (__nv_bfloat16*)p;
    cudaGetSymbolAddress(&p, g_inKh); inKh = (__nv_bfloat16*)p;
    cudaGetSymbolAddress(&p, g_inKl); inKl = (__nv_bfloat16*)p;
    cudaGetSymbolAddress(&p, g_inVh); inVh = (__nv_bfloat16*)p;
    cudaGetSymbolAddress(&p, g_inVl); inVl = (__nv_bfloat16*)p;
    cudaGetSymbolAddress(&p, g_Wqh);  wqh = (__nv_bfloat16*)p;
    cudaGetSymbolAddress(&p, g_Wql);  wql = (__nv_bfloat16*)p;
    cudaGetSymbolAddress(&p, g_Wkh);  wkh = (__nv_bfloat16*)p;
    cudaGetSymbolAddress(&p, g_Wkl);  wkl = (__nv_bfloat16*)p;
    cudaGetSymbolAddress(&p, g_Wvh);  wvh = (__nv_bfloat16*)p;
    cudaGetSymbolAddress(&p, g_Wvl);  wvl = (__nv_bfloat16*)p;
    cudaGetSymbolAddress(&p, g_Wfh);  wfh = (__nv_bfloat16*)p;
    cudaGetSymbolAddress(&p, g_Wfl);  wfl = (__nv_bfloat16*)p;
    cudaGetSymbolAddress(&p, g_ctxh); cth = (__nv_bfloat16*)p;
    cudaGetSymbolAddress(&p, g_ctxl); ctl = (__nv_bfloat16*)p;

    static int attr_set = 0;
    if (!attr_set) {
        cudaFuncSetAttribute(mma_gemm<0,0>, cudaFuncAttributeMaxDynamicSharedMemorySize, 65536);
        cudaFuncSetAttribute(mma_gemm<1,0>, cudaFuncAttributeMaxDynamicSharedMemorySize, 65536);
        cudaFuncSetAttribute(mma_gemm<3,1>, cudaFuncAttributeMaxDynamicSharedMemorySize, 65536);
        cudaFuncSetAttribute(mma_gemm<2,1>, cudaFuncAttributeMaxDynamicSharedMemorySize, 73728);
        attr_set = 1;
    }

    detect_mask_kernel<<<1, 256>>>(msk);
    mask_to_bits<<<(BB * SQ * SQ / 32) / 8, 256>>>(msk);

    // pre-split all inputs + weights in ONE launch
    const int NIN4 = ROWS * DM / 4, NW4 = DM * DM / 4;
    ConvArgs ca;
    ca.src[0] = (const float4*)iQ;  ca.hi[0] = (uint2*)inQh; ca.lo[0] = (uint2*)inQl; ca.n4[0] = NIN4;
    ca.src[1] = (const float4*)iK;  ca.hi[1] = (uint2*)inKh; ca.lo[1] = (uint2*)inKl; ca.n4[1] = NIN4;
    ca.src[2] = (const float4*)iV;  ca.hi[2] = (uint2*)inVh; ca.lo[2] = (uint2*)inVl; ca.n4[2] = NIN4;
    ca.src[3] = (const float4*)WQ;  ca.hi[3] = (uint2*)wqh;  ca.lo[3] = (uint2*)wql;  ca.n4[3] = NW4;
    ca.src[4] = (const float4*)WK;  ca.hi[4] = (uint2*)wkh;  ca.lo[4] = (uint2*)wkl;  ca.n4[4] = NW4;
    ca.src[5] = (const float4*)WV;  ca.hi[5] = (uint2*)wvh;  ca.lo[5] = (uint2*)wvl;  ca.n4[5] = NW4;
    ca.src[6] = (const float4*)Wfc; ca.hi[6] = (uint2*)wfh;  ca.lo[6] = (uint2*)wfl;  ca.n4[6] = NW4;
    convert_all<<<dim3(NIN4 / 256, 7), 256>>>(ca);

    // packed Q/K/V projections: one launch, z selects the GEMM
    dim3 gqkv(DM / 128, ROWS / 128, 3);          // (8, 32, 3)
    mma_gemm<3,1><<<gqkv, 256, 65536>>>(nullptr, nullptr, nullptr, nullptr, nullptr,
                                        nullptr, nullptr, nullptr);

    // qk scores -> g_attn scratch
    dim3 gs(SQ / 128, SQ / 128, BHN);            // (16, 16, 32)
    mma_gemm<1,0><<<gs, 256, 65536>>>(nullptr, nullptr, nullptr, nullptr, nullptr, pAttn, nullptr, nullptr);

    float* attn_dst = attn_out ? attn_out : pAttn;
    softmax_rows<<<(unsigned)(BHN * SQ), 256>>>(pAttn, attn_dst);

    // pv: attn f32 (cp.async staged) + V split bf16 -> ctx split bf16
    dim3 gv(1, SQ / 128, BHN);                   // (1, 16, 32)
    mma_gemm<2,1><<<gv, 256, 73728>>>(attn_dst, nullptr, nullptr, nullptr, nullptr, nullptr, nullptr, nullptr);

    // fc: ctx bf16 @ Wfc bf16 -> f32
    dim3 gp(DM / 128, ROWS / 128);               // (8, 32)
    mma_gemm<0,0><<<gp, 256, 65536>>>(nullptr, cth, ctl, wfh, wfl, pFc, nullptr, nullptr);

    add_ln<<<(unsigned)ROWS, 256>>>(iQ, ln_out);
}